// round 3
// baseline (speedup 1.0000x reference)
#include <cuda_runtime.h>
#include <cuda_bf16.h>

// ---------------------------------------------------------------------------
// BottomUpHTMM — complete 4-ary tree depth 7.
// limits = {0,1,5,21,85,341,1365,5461,21845}; G=16, C=8, L=4, M=256.
// Key simplifications:
//  * prior is node-independent per level and cancels everywhere -> dropped.
//  * leaf beta recomputed inline (pit*bt normalized); leaf eps never stored
//    (its b_lh+pi_lh contribution accumulated in down6).
//  * levels 2,1,0 of up+down fused into one single-block kernel (mid, 512 thr).
// State arrays cover internal nodes only: [node][g][c], c fastest.
// ---------------------------------------------------------------------------

#define T_SIZE 21845
#define N_INT  5461
#define GC     128

__device__ float g_sbeta[N_INT * GC];
__device__ float g_beta [N_INT * GC];
__device__ float g_eps  [N_INT * GC];

// tables
__device__ float g_asp [4096];       // a_sp[g][i][l][j]  (tid=g*8+i -> tid*32+l*8+j)
__device__ float g_loga[4096];       // log sm_a, same layout
__device__ float g_bt  [16*256*8];   // sm_b[g][m][c]
__device__ float g_lbt [16*256*8];
__device__ float g_pit [16*4*8];     // sm_pi[g][pos][c]
__device__ float g_lpit[16*4*8];
__device__ float g_lsp [64];         // log sm_sp[g][l]

// partial-sum slots (one per down block)
#define SLOT_MID 0
#define SLOT_D3  1
#define SLOT_D4  65
#define SLOT_D5  321
#define SLOT_D6  1345
#define NSLOT    5441
__device__ float g_partial[NSLOT * 16];

// ---------------------------------------------------------------------------
__device__ __forceinline__ float sum8(float v) {
    v += __shfl_xor_sync(0xffffffffu, v, 4);
    v += __shfl_xor_sync(0xffffffffu, v, 2);
    v += __shfl_xor_sync(0xffffffffu, v, 1);
    return v;
}

__device__ __forceinline__ void load_tab(const float* __restrict__ base, int tid,
                                         float (&r)[4][8]) {
    const float4* p = (const float4*)(base + tid * 32);
    #pragma unroll
    for (int l = 0; l < 4; l++) {
        float4 a = p[2*l], b = p[2*l + 1];
        r[l][0]=a.x; r[l][1]=a.y; r[l][2]=a.z; r[l][3]=a.w;
        r[l][4]=b.x; r[l][5]=b.y; r[l][6]=b.z; r[l][7]=b.w;
    }
}

// ---------------------------------------------------------------------------
// prep: softmaxes + logs into tables.
// ---------------------------------------------------------------------------
__global__ void __launch_bounds__(256) prep_kernel(const float* __restrict__ a,
                            const float* __restrict__ b,
                            const float* __restrict__ pi,
                            const float* __restrict__ sp)
{
    const int t = threadIdx.x;           // 256
    if (blockIdx.x == 0) {
        __shared__ float s_sp[64];
        if (t < 16) {
            float v[4]; float mx = -1e30f;
            #pragma unroll
            for (int l = 0; l < 4; l++) { v[l] = sp[t*4 + l]; mx = fmaxf(mx, v[l]); }
            float s = 0.f;
            #pragma unroll
            for (int l = 0; l < 4; l++) { v[l] = expf(v[l] - mx); s += v[l]; }
            float inv = 1.f / s;
            #pragma unroll
            for (int l = 0; l < 4; l++) {
                float sm = v[l] * inv;
                s_sp[t*4 + l]  = sm;
                g_lsp[t*4 + l] = logf(sm);
            }
        }
        if (t < 64) {
            int g = t >> 2, l = t & 3;
            float v[8]; float mx = -1e30f;
            #pragma unroll
            for (int c = 0; c < 8; c++) { v[c] = pi[g*32 + c*4 + l]; mx = fmaxf(mx, v[c]); }
            float s = 0.f;
            #pragma unroll
            for (int c = 0; c < 8; c++) { v[c] = expf(v[c] - mx); s += v[c]; }
            float inv = 1.f / s, ls = logf(s);
            #pragma unroll
            for (int c = 0; c < 8; c++) {
                g_pit [g*32 + l*8 + c] = v[c] * inv;
                g_lpit[g*32 + l*8 + c] = logf(v[c]) - ls;
            }
        }
        __syncthreads();
        // sm_a: softmax over i (axis 1), 512 (g,j,l) groups
        for (int grp = t; grp < 512; grp += 256) {
            int g = grp >> 5, j = (grp >> 2) & 7, l = grp & 3;
            float v[8]; float mx = -1e30f;
            #pragma unroll
            for (int i = 0; i < 8; i++) {
                v[i] = a[g*256 + i*32 + j*4 + l];
                mx = fmaxf(mx, v[i]);
            }
            float s = 0.f;
            #pragma unroll
            for (int i = 0; i < 8; i++) { v[i] = expf(v[i] - mx); s += v[i]; }
            float inv = 1.f / s, ls = logf(s);
            float spv = s_sp[g*4 + l];
            #pragma unroll
            for (int i = 0; i < 8; i++) {
                int idx = ((g*8 + i)*4 + l)*8 + j;
                float sm = v[i] * inv;
                g_asp [idx] = sm * spv;
                g_loga[idx] = logf(v[i]) - ls;
            }
        }
    } else {
        int g = blockIdx.x - 1;
        int w = t >> 5, lane = t & 31;
        const float* bp = b + (g*8 + w) * 256;
        float mx = -1e30f;
        for (int m = lane; m < 256; m += 32) mx = fmaxf(mx, bp[m]);
        #pragma unroll
        for (int o = 16; o; o >>= 1) mx = fmaxf(mx, __shfl_xor_sync(0xffffffffu, mx, o));
        float s = 0.f;
        for (int m = lane; m < 256; m += 32) s += expf(bp[m] - mx);
        #pragma unroll
        for (int o = 16; o; o >>= 1) s += __shfl_xor_sync(0xffffffffu, s, o);
        float inv = 1.f / s, ls = logf(s);
        for (int m = lane; m < 256; m += 32) {
            float e = bp[m] - mx;
            g_bt [g*2048 + m*8 + w] = expf(e) * inv;
            g_lbt[g*2048 + m*8 + w] = e - ls;
        }
    }
}

// ---------------------------------------------------------------------------
// up level 6 (block per node, leaf children computed inline)
// ---------------------------------------------------------------------------
__global__ void __launch_bounds__(128) up6_kernel(const int* __restrict__ tn)
{
    const int u = 1365 + blockIdx.x;
    const int tid = threadIdx.x, g = tid >> 3, c = tid & 7;
    float as[4][8]; load_tab(g_asp, tid, as);
    __shared__ int   slab[4];
    __shared__ float sbc[512];
    if (tid < 4) slab[tid] = tn[(4*u + 1 + tid) * 7];
    int labu = tn[u * 7];
    __syncthreads();
    #pragma unroll
    for (int l = 0; l < 4; l++) {
        float v = g_pit[g*32 + l*8 + c] * g_bt[g*2048 + slab[l]*8 + c];
        float sv = sum8(v);
        sbc[l*128 + tid] = v / sv;
    }
    __syncthreads();
    float sb = 0.f;
    #pragma unroll
    for (int l = 0; l < 4; l++) {
        const float* bv = &sbc[l*128 + g*8];
        #pragma unroll
        for (int j = 0; j < 8; j++) sb += as[l][j] * bv[j];
    }
    float tmp = g_bt[g*2048 + labu*8 + c] * sb;
    float ts = sum8(tmp);
    g_sbeta[u*GC + tid] = sb;
    g_beta [u*GC + tid] = tmp / ts;
}

// ---------------------------------------------------------------------------
// up generic level (block per node, internal children)
// ---------------------------------------------------------------------------
__global__ void __launch_bounds__(128) up_kernel(const int* __restrict__ tn, int s)
{
    const int u = s + blockIdx.x;
    const int tid = threadIdx.x, g = tid >> 3, i = tid & 7;
    float as[4][8]; load_tab(g_asp, tid, as);
    __shared__ float sbc[512];
    ((float4*)sbc)[tid] = *(const float4*)&g_beta[(4*u + 1)*GC + tid*4];
    int labu = tn[u * 7];
    __syncthreads();
    float sb = 0.f;
    #pragma unroll
    for (int l = 0; l < 4; l++) {
        const float* bv = &sbc[l*128 + g*8];
        #pragma unroll
        for (int j = 0; j < 8; j++) sb += as[l][j] * bv[j];
    }
    float tmp = g_bt[g*2048 + labu*8 + i] * sb;
    float ts = sum8(tmp);
    g_sbeta[u*GC + tid] = sb;
    g_beta [u*GC + tid] = tmp / ts;
}

// ---------------------------------------------------------------------------
// down generic level (block per node, internal children; writes child eps)
// ---------------------------------------------------------------------------
__global__ void __launch_bounds__(128) down_kernel(const int* __restrict__ tn, int s, int slotBase)
{
    const int u = s + blockIdx.x;
    const int tid = threadIdx.x, g = tid >> 3, i = tid & 7;
    float as[4][8], la[4][8];
    load_tab(g_asp, tid, as);
    load_tab(g_loga, tid, la);
    #pragma unroll
    for (int l = 0; l < 4; l++)
        #pragma unroll
        for (int j = 0; j < 8; j++) la[l][j] *= as[l][j];
    float lsp[4];
    #pragma unroll
    for (int l = 0; l < 4; l++) lsp[l] = g_lsp[g*4 + l];

    __shared__ float sbc[512];
    __shared__ float sred[16];
    ((float4*)sbc)[tid] = *(const float4*)&g_beta[(4*u + 1)*GC + tid*4];
    float epsv = g_eps[u*GC + tid];
    float pe = epsv / g_sbeta[u*GC + tid];
    int labu = tn[u * 7];
    float acc = epsv * g_lbt[g*2048 + labu*8 + i];
    __syncthreads();
    #pragma unroll
    for (int l = 0; l < 4; l++) {
        const float* bv = &sbc[l*128 + g*8];
        float ce = 0.f, ca = 0.f;
        #pragma unroll
        for (int j = 0; j < 8; j++) { ce += as[l][j]*bv[j]; ca += la[l][j]*bv[j]; }
        ce *= pe;
        g_eps[(4*u + 1 + l)*GC + tid] = ce;
        acc += pe*ca + lsp[l]*ce;
    }
    acc = sum8(acc);
    if (i == 0) sred[g] = acc;
    __syncthreads();
    if (tid < 16) g_partial[(slotBase + blockIdx.x)*16 + tid] = sred[tid];
}

// ---------------------------------------------------------------------------
// down level 6 (leaf children inline; accumulates leaf b_lh + pi_lh; no eps store)
// ---------------------------------------------------------------------------
__global__ void __launch_bounds__(128) down6_kernel(const int* __restrict__ tn, int slotBase)
{
    const int u = 1365 + blockIdx.x;
    const int tid = threadIdx.x, g = tid >> 3, i = tid & 7;
    float as[4][8], la[4][8];
    load_tab(g_asp, tid, as);
    load_tab(g_loga, tid, la);
    #pragma unroll
    for (int l = 0; l < 4; l++)
        #pragma unroll
        for (int j = 0; j < 8; j++) la[l][j] *= as[l][j];
    float lsp[4];
    #pragma unroll
    for (int l = 0; l < 4; l++) lsp[l] = g_lsp[g*4 + l];

    __shared__ int   slab[4];
    __shared__ float sbc[512];
    __shared__ float sred[16];
    if (tid < 4) slab[tid] = tn[(4*u + 1 + tid) * 7];
    float epsv = g_eps[u*GC + tid];
    float pe = epsv / g_sbeta[u*GC + tid];
    int labu = tn[u * 7];
    float acc = epsv * g_lbt[g*2048 + labu*8 + i];
    __syncthreads();
    #pragma unroll
    for (int l = 0; l < 4; l++) {
        float v = g_pit[g*32 + l*8 + i] * g_bt[g*2048 + slab[l]*8 + i];
        float sv = sum8(v);
        sbc[l*128 + tid] = v / sv;
    }
    __syncthreads();
    #pragma unroll
    for (int l = 0; l < 4; l++) {
        const float* bv = &sbc[l*128 + g*8];
        float ce = 0.f, ca = 0.f;
        #pragma unroll
        for (int j = 0; j < 8; j++) { ce += as[l][j]*bv[j]; ca += la[l][j]*bv[j]; }
        ce *= pe;
        float w = lsp[l] + g_lbt[g*2048 + slab[l]*8 + i] + g_lpit[g*32 + l*8 + i];
        acc += pe*ca + w*ce;
    }
    acc = sum8(acc);
    if (i == 0) sred[g] = acc;
    __syncthreads();
    if (tid < 16) g_partial[(slotBase + blockIdx.x)*16 + tid] = sred[tid];
}

// ---------------------------------------------------------------------------
// mid: up levels 2,1,0 + down levels 0,1,2 in ONE block (512 thr = 4 groups).
// Root up+down fused in registers (root beta/sbeta never stored).
// ---------------------------------------------------------------------------
__global__ void __launch_bounds__(512, 1) mid_kernel(const int* __restrict__ tn)
{
    const int tid = threadIdx.x;         // 512
    const int q = tid >> 7, wt = tid & 127, g = wt >> 3, i = wt & 7;
    float as[4][8], la[4][8];
    load_tab(g_asp, wt, as);
    load_tab(g_loga, wt, la);
    #pragma unroll
    for (int l = 0; l < 4; l++)
        #pragma unroll
        for (int j = 0; j < 8; j++) la[l][j] *= as[l][j];
    float lsp[4];
    #pragma unroll
    for (int l = 0; l < 4; l++) lsp[l] = g_lsp[g*4 + l];

    __shared__ float sbc[2048];
    __shared__ float sred[4][16];
    float* slice = sbc + q*512;
    float acc = 0.f;

    // ---- UP level 2: nodes 5..20 (4 rounds of 4) ----
    #pragma unroll
    for (int r = 0; r < 4; r++) {
        int u = 5 + r*4 + q;
        ((float4*)slice)[wt] = *(const float4*)&g_beta[(4*u + 1)*GC + wt*4];
        __syncthreads();
        float sb = 0.f;
        #pragma unroll
        for (int l = 0; l < 4; l++) {
            const float* bv = &slice[l*128 + g*8];
            #pragma unroll
            for (int j = 0; j < 8; j++) sb += as[l][j]*bv[j];
        }
        int labu = tn[u*7];
        float tmp = g_bt[g*2048 + labu*8 + i] * sb;
        float ts = sum8(tmp);
        g_sbeta[u*GC + wt] = sb;
        g_beta [u*GC + wt] = tmp / ts;
        __syncthreads();
    }
    // ---- UP level 1: nodes 1..4 ----
    {
        int u = 1 + q;
        ((float4*)slice)[wt] = *(const float4*)&g_beta[(4*u + 1)*GC + wt*4];
        __syncthreads();
        float sb = 0.f;
        #pragma unroll
        for (int l = 0; l < 4; l++) {
            const float* bv = &slice[l*128 + g*8];
            #pragma unroll
            for (int j = 0; j < 8; j++) sb += as[l][j]*bv[j];
        }
        int labu = tn[u*7];
        float tmp = g_bt[g*2048 + labu*8 + i] * sb;
        float ts = sum8(tmp);
        g_sbeta[u*GC + wt] = sb;
        g_beta [u*GC + wt] = tmp / ts;
        __syncthreads();
    }
    // ---- UP level 0 + DOWN level 0 fused (q==0) ----
    if (q == 0) ((float4*)slice)[wt] = *(const float4*)&g_beta[1*GC + wt*4];
    __syncthreads();
    if (q == 0) {
        float sb = 0.f;
        #pragma unroll
        for (int l = 0; l < 4; l++) {
            const float* bv = &slice[l*128 + g*8];
            #pragma unroll
            for (int j = 0; j < 8; j++) sb += as[l][j]*bv[j];
        }
        int lab0 = tn[0];
        float tmp = g_bt[g*2048 + lab0*8 + i] * sb;
        float ts = sum8(tmp);
        float betar = tmp / ts;           // root beta = root eps
        float pe = betar / sb;
        acc += betar * g_lbt[g*2048 + lab0*8 + i];
        #pragma unroll
        for (int l = 0; l < 4; l++) {
            const float* bv = &slice[l*128 + g*8];
            float ce = 0.f, ca = 0.f;
            #pragma unroll
            for (int j = 0; j < 8; j++) { ce += as[l][j]*bv[j]; ca += la[l][j]*bv[j]; }
            ce *= pe;
            g_eps[(1 + l)*GC + wt] = ce;
            acc += pe*ca + lsp[l]*ce;
        }
    }
    __syncthreads();
    // ---- DOWN level 1: nodes 1..4 ----
    {
        int u = 1 + q;
        ((float4*)slice)[wt] = *(const float4*)&g_beta[(4*u + 1)*GC + wt*4];
        __syncthreads();
        float epsv = g_eps[u*GC + wt];
        float pe = epsv / g_sbeta[u*GC + wt];
        int labu = tn[u*7];
        acc += epsv * g_lbt[g*2048 + labu*8 + i];
        #pragma unroll
        for (int l = 0; l < 4; l++) {
            const float* bv = &slice[l*128 + g*8];
            float ce = 0.f, ca = 0.f;
            #pragma unroll
            for (int j = 0; j < 8; j++) { ce += as[l][j]*bv[j]; ca += la[l][j]*bv[j]; }
            ce *= pe;
            g_eps[(4*u + 1 + l)*GC + wt] = ce;
            acc += pe*ca + lsp[l]*ce;
        }
        __syncthreads();
    }
    // ---- DOWN level 2: nodes 5..20 (4 rounds of 4) ----
    #pragma unroll
    for (int r = 0; r < 4; r++) {
        int u = 5 + r*4 + q;
        ((float4*)slice)[wt] = *(const float4*)&g_beta[(4*u + 1)*GC + wt*4];
        __syncthreads();
        float epsv = g_eps[u*GC + wt];
        float pe = epsv / g_sbeta[u*GC + wt];
        int labu = tn[u*7];
        acc += epsv * g_lbt[g*2048 + labu*8 + i];
        #pragma unroll
        for (int l = 0; l < 4; l++) {
            const float* bv = &slice[l*128 + g*8];
            float ce = 0.f, ca = 0.f;
            #pragma unroll
            for (int j = 0; j < 8; j++) { ce += as[l][j]*bv[j]; ca += la[l][j]*bv[j]; }
            ce *= pe;
            g_eps[(4*u + 1 + l)*GC + wt] = ce;
            acc += pe*ca + lsp[l]*ce;
        }
        __syncthreads();
    }
    // ---- block reduce ----
    acc = sum8(acc);
    if (i == 0) sred[q][g] = acc;
    __syncthreads();
    if (tid < 16) {
        float s = 0.f;
        #pragma unroll
        for (int k = 0; k < 4; k++) s += sred[k][tid];
        g_partial[SLOT_MID*16 + tid] = s;
    }
}

// ---------------------------------------------------------------------------
__global__ void __launch_bounds__(1024) combine_kernel(float* __restrict__ out)
{
    const int tid = threadIdx.x;   // 1024 (multiple of 16 -> tid&15 stable per thread)
    __shared__ float sacc[16];
    if (tid < 16) sacc[tid] = 0.f;
    __syncthreads();
    float acc = 0.f;
    for (int f = tid; f < NSLOT*16; f += 1024) acc += g_partial[f];
    atomicAdd(&sacc[tid & 15], acc);
    __syncthreads();
    if (tid < 16) out[tid] = sacc[tid];
}

// ---------------------------------------------------------------------------
extern "C" void kernel_launch(void* const* d_in, const int* in_sizes, int n_in,
                              void* d_out, int out_size)
{
    const int*   tn = (const int*)  d_in[0];
    const float* a  = (const float*)d_in[2];
    const float* b  = (const float*)d_in[3];
    const float* pi = (const float*)d_in[4];
    const float* sp = (const float*)d_in[5];
    float* out = (float*)d_out;

    prep_kernel<<<17, 256>>>(a, b, pi, sp);
    up6_kernel<<<4096, 128>>>(tn);
    up_kernel<<<1024, 128>>>(tn, 341);
    up_kernel<<<256, 128>>>(tn, 85);
    up_kernel<<<64, 128>>>(tn, 21);
    mid_kernel<<<1, 512>>>(tn);
    down_kernel<<<64, 128>>>(tn, 21, SLOT_D3);
    down_kernel<<<256, 128>>>(tn, 85, SLOT_D4);
    down_kernel<<<1024, 128>>>(tn, 341, SLOT_D5);
    down6_kernel<<<4096, 128>>>(tn, SLOT_D6);
    combine_kernel<<<1, 1024>>>(out);
}

// round 4
// speedup vs baseline: 1.4721x; 1.4721x over previous
#include <cuda_runtime.h>

// ---------------------------------------------------------------------------
// BottomUpHTMM — complete 4-ary tree depth 7, single persistent kernel.
// limits = {0,1,5,21,85,341,1365,5461,21845}; G=16, C=8, L=4, M=256.
// 64 blocks (one per level-3 subtree), 512 threads (4 groups of 128 = (g,c)).
// Phases separated by a software grid barrier (all 64 blocks co-resident:
// grid <= #SMs, 1 block/SM by smem).
// ---------------------------------------------------------------------------

#define GC 128

// tables
__device__ float g_asp [4096];      // a_sp[g][i][l][j]   (wt=g*8+i -> wt*32+l*8+j)
__device__ float g_loga[4096];      // log sm_a
__device__ float g_bt  [16*256*8];  // sm_b[g][m][c]
__device__ float g_lbt [16*256*8];
__device__ float g_pit [512];       // sm_pi[g][pos][c]
__device__ float g_lpit[512];
__device__ float g_lsp [64];        // log sm_sp[g][l]

// cross-block state
__device__ float g_beta3[64 * GC];
__device__ float g_eps3 [64 * GC];
__device__ float g_accum[16];

// grid barrier
__device__ unsigned g_cnt = 0;
__device__ unsigned g_gen = 0;

// shared-memory layout (floats)
#define OFF_BETA   0        // 84*128: lvl4 k:0..3, lvl5 4+k:4..19, lvl6 20+k:20..83
#define OFF_SBETA  10752    // 85*128: lvl3:0, lvl4 1+k, lvl5 5+k, lvl6 21+k
#define OFF_BUFA   21632    // 20*128
#define OFF_BUFB   24192    // 64*128
#define OFF_TOPB   32384    // 20*128: lvl2 0..15, lvl1 16..19 (block 0 only)
#define OFF_TOPSB  34944    // 20*128
#define OFF_EPS1   37504    // 4*128
#define OFF_RED    38016    // 64
#define SMEM_FLOATS 38080   // 152320 bytes

__device__ __forceinline__ float sum8(float v) {
    v += __shfl_xor_sync(0xffffffffu, v, 4);
    v += __shfl_xor_sync(0xffffffffu, v, 2);
    v += __shfl_xor_sync(0xffffffffu, v, 1);
    return v;
}

__device__ __forceinline__ void load_tab(const float* __restrict__ base, int wt,
                                         float (&r)[4][8]) {
    const float4* p = (const float4*)(base + wt * 32);
    #pragma unroll
    for (int l = 0; l < 4; l++) {
        float4 a = p[2*l], b = p[2*l + 1];
        r[l][0]=a.x; r[l][1]=a.y; r[l][2]=a.z; r[l][3]=a.w;
        r[l][4]=b.x; r[l][5]=b.y; r[l][6]=b.z; r[l][7]=b.w;
    }
}

// sense-reversing grid barrier for exactly 64 blocks
__device__ __forceinline__ void gbar() {
    __syncthreads();
    if (threadIdx.x == 0) {
        __threadfence();
        unsigned gen = atomicAdd(&g_gen, 0u);
        unsigned old = atomicAdd(&g_cnt, 1u);
        if (old == 63u) {
            atomicExch(&g_cnt, 0u);
            __threadfence();
            atomicAdd(&g_gen, 1u);
        } else {
            while (atomicAdd(&g_gen, 0u) == gen) __nanosleep(64);
        }
        __threadfence();
    }
    __syncthreads();
}

// up-step dot: sb = sum_l sum_j as[l][j] * cb[l][g*8+j]
__device__ __forceinline__ float dot_up(const float* __restrict__ cb0, int stride,
                                        const float (&as)[4][8], int g) {
    float sb = 0.f;
    #pragma unroll
    for (int l = 0; l < 4; l++) {
        const float* bv = cb0 + l*stride + g*8;
        #pragma unroll
        for (int j = 0; j < 8; j++) sb += as[l][j] * bv[j];
    }
    return sb;
}

__global__ void __launch_bounds__(512, 1)
main_kernel(const int* __restrict__ tn,
            const float* __restrict__ a,
            const float* __restrict__ b,
            const float* __restrict__ pi,
            const float* __restrict__ sp,
            float* __restrict__ out)
{
    extern __shared__ float sm[];
    const int tid = threadIdx.x, s = blockIdx.x;
    const int q = tid >> 7, wt = tid & 127, g = wt >> 3, i = wt & 7;
    const int lane = tid & 31;

    // ================= phase 0: prep =================
    if (s < 16) {
        if (tid < 256) {
            int w = tid >> 5, ln = tid & 31;
            const float* bp = b + (s*8 + w) * 256;
            float mx = -1e30f;
            for (int m = ln; m < 256; m += 32) mx = fmaxf(mx, bp[m]);
            #pragma unroll
            for (int o = 16; o; o >>= 1) mx = fmaxf(mx, __shfl_xor_sync(0xffffffffu, mx, o));
            float ssum = 0.f;
            for (int m = ln; m < 256; m += 32) ssum += expf(bp[m] - mx);
            #pragma unroll
            for (int o = 16; o; o >>= 1) ssum += __shfl_xor_sync(0xffffffffu, ssum, o);
            float inv = 1.f / ssum, ls = logf(ssum);
            for (int m = ln; m < 256; m += 32) {
                float e = bp[m] - mx;
                g_bt [s*2048 + m*8 + w] = expf(e) * inv;
                g_lbt[s*2048 + m*8 + w] = e - ls;
            }
        }
    } else if (s == 16) {
        float* s_sp = sm + OFF_RED;   // 64 floats scratch
        if (tid < 16) {
            float v[4]; float mx = -1e30f;
            #pragma unroll
            for (int l = 0; l < 4; l++) { v[l] = sp[tid*4 + l]; mx = fmaxf(mx, v[l]); }
            float su = 0.f;
            #pragma unroll
            for (int l = 0; l < 4; l++) { v[l] = expf(v[l] - mx); su += v[l]; }
            float inv = 1.f / su;
            #pragma unroll
            for (int l = 0; l < 4; l++) {
                float smv = v[l] * inv;
                s_sp[tid*4 + l]  = smv;
                g_lsp[tid*4 + l] = logf(smv);
            }
        }
        if (tid < 64) {
            int gg = tid >> 2, l = tid & 3;
            float v[8]; float mx = -1e30f;
            #pragma unroll
            for (int c = 0; c < 8; c++) { v[c] = pi[gg*32 + c*4 + l]; mx = fmaxf(mx, v[c]); }
            float su = 0.f;
            #pragma unroll
            for (int c = 0; c < 8; c++) { v[c] = expf(v[c] - mx); su += v[c]; }
            float inv = 1.f / su, ls = logf(su);
            #pragma unroll
            for (int c = 0; c < 8; c++) {
                g_pit [gg*32 + l*8 + c] = v[c] * inv;
                g_lpit[gg*32 + l*8 + c] = logf(v[c]) - ls;
            }
        }
        __syncthreads();
        {   // sm_a: 512 (g,j,l) groups, one per thread
            int grp = tid;
            int gg = grp >> 5, j = (grp >> 2) & 7, l = grp & 3;
            float v[8]; float mx = -1e30f;
            #pragma unroll
            for (int ii = 0; ii < 8; ii++) {
                v[ii] = a[gg*256 + ii*32 + j*4 + l];
                mx = fmaxf(mx, v[ii]);
            }
            float su = 0.f;
            #pragma unroll
            for (int ii = 0; ii < 8; ii++) { v[ii] = expf(v[ii] - mx); su += v[ii]; }
            float inv = 1.f / su, ls = logf(su);
            float spv = s_sp[gg*4 + l];
            #pragma unroll
            for (int ii = 0; ii < 8; ii++) {
                int idx = ((gg*8 + ii)*4 + l)*8 + j;
                g_asp [idx] = v[ii] * inv * spv;
                g_loga[idx] = logf(v[ii]) - ls;
            }
        }
    } else if (s == 17) {
        if (tid < 16) g_accum[tid] = 0.f;
    }
    gbar();

    // constant tables in registers
    float as[4][8], la[4][8];
    load_tab(g_asp, wt, as);
    load_tab(g_loga, wt, la);
    #pragma unroll
    for (int l = 0; l < 4; l++)
        #pragma unroll
        for (int j = 0; j < 8; j++) la[l][j] *= as[l][j];
    float lsp[4];
    #pragma unroll
    for (int l = 0; l < 4; l++) lsp[l] = g_lsp[g*4 + l];

    // ================= phase 1: subtree up =================
    // lvl6 (64 nodes): leaf children recomputed inline
    #pragma unroll 1
    for (int rr = 0; rr < 16; rr++) {
        int k = rr*4 + q;
        int u6 = 1365 + 64*s + k;
        int Lb = 4*u6 + 1;
        int pre = (lane < 4) ? tn[(Lb + lane)*7] : (lane == 4 ? tn[u6*7] : 0);
        float sb = 0.f;
        #pragma unroll
        for (int l = 0; l < 4; l++) {
            int labl = __shfl_sync(0xffffffffu, pre, l);
            float lb = g_pit[g*32 + l*8 + i] * g_bt[g*2048 + labl*8 + i];
            lb /= sum8(lb);
            #pragma unroll
            for (int j = 0; j < 8; j++)
                sb += as[l][j] * __shfl_sync(0xffffffffu, lb, j, 8);
        }
        int labu = __shfl_sync(0xffffffffu, pre, 4);
        float tmp = g_bt[g*2048 + labu*8 + i] * sb;
        float ts = sum8(tmp);
        sm[OFF_BETA  + (20 + k)*128 + wt] = tmp / ts;
        sm[OFF_SBETA + (21 + k)*128 + wt] = sb;
    }
    __syncthreads();
    // lvl5 (16)
    #pragma unroll 1
    for (int rr = 0; rr < 4; rr++) {
        int k = rr*4 + q;
        float sb = dot_up(sm + OFF_BETA + (20 + 4*k)*128, 128, as, g);
        int labu = tn[(341 + 16*s + k)*7];
        float tmp = g_bt[g*2048 + labu*8 + i] * sb;
        float ts = sum8(tmp);
        sm[OFF_BETA  + (4 + k)*128 + wt] = tmp / ts;
        sm[OFF_SBETA + (5 + k)*128 + wt] = sb;
    }
    __syncthreads();
    // lvl4 (4)
    {
        float sb = dot_up(sm + OFF_BETA + (4 + 4*q)*128, 128, as, g);
        int labu = tn[(85 + 4*s + q)*7];
        float tmp = g_bt[g*2048 + labu*8 + i] * sb;
        float ts = sum8(tmp);
        sm[OFF_BETA  + q*128 + wt]       = tmp / ts;
        sm[OFF_SBETA + (1 + q)*128 + wt] = sb;
    }
    __syncthreads();
    // lvl3 (subtree root)
    if (q == 0) {
        float sb = dot_up(sm + OFF_BETA, 128, as, g);
        int labu = tn[(21 + s)*7];
        float tmp = g_bt[g*2048 + labu*8 + i] * sb;
        float ts = sum8(tmp);
        g_beta3[s*128 + wt] = tmp / ts;
        sm[OFF_SBETA + wt] = sb;
    }
    gbar();

    // ================= phase 2: top levels (block 0 only) =================
    float acc = 0.f;
    if (s == 0) {
        for (int idx = tid; idx < 64*128; idx += 512)
            sm[OFF_BUFB + idx] = g_beta3[idx];
        __syncthreads();
        // up lvl2 (16)
        #pragma unroll 1
        for (int rr = 0; rr < 4; rr++) {
            int k = rr*4 + q;
            float sb = dot_up(sm + OFF_BUFB + 4*k*128, 128, as, g);
            int labu = tn[(5 + k)*7];
            float tmp = g_bt[g*2048 + labu*8 + i] * sb;
            float ts = sum8(tmp);
            sm[OFF_TOPB  + k*128 + wt] = tmp / ts;
            sm[OFF_TOPSB + k*128 + wt] = sb;
        }
        __syncthreads();
        // up lvl1 (4)
        {
            float sb = dot_up(sm + OFF_TOPB + 4*q*128, 128, as, g);
            int labu = tn[(1 + q)*7];
            float tmp = g_bt[g*2048 + labu*8 + i] * sb;
            float ts = sum8(tmp);
            sm[OFF_TOPB  + (16 + q)*128 + wt] = tmp / ts;
            sm[OFF_TOPSB + (16 + q)*128 + wt] = sb;
        }
        __syncthreads();
        // lvl0 up+down fused
        if (q == 0) {
            float sb = dot_up(sm + OFF_TOPB + 16*128, 128, as, g);
            int lab0 = tn[0];
            float tmp = g_bt[g*2048 + lab0*8 + i] * sb;
            float ts = sum8(tmp);
            float betar = tmp / ts;
            float pe = betar / sb;
            acc += betar * g_lbt[g*2048 + lab0*8 + i];
            #pragma unroll
            for (int l = 0; l < 4; l++) {
                const float* bv = sm + OFF_TOPB + (16 + l)*128 + g*8;
                float ce = 0.f, ca = 0.f;
                #pragma unroll
                for (int j = 0; j < 8; j++) { ce += as[l][j]*bv[j]; ca += la[l][j]*bv[j]; }
                ce *= pe;
                sm[OFF_EPS1 + l*128 + wt] = ce;
                acc += pe*ca + lsp[l]*ce;
            }
        }
        __syncthreads();
        // down lvl1 (4)
        {
            float epsv = sm[OFF_EPS1 + q*128 + wt];
            float pe = epsv / sm[OFF_TOPSB + (16 + q)*128 + wt];
            int labu = tn[(1 + q)*7];
            acc += epsv * g_lbt[g*2048 + labu*8 + i];
            #pragma unroll
            for (int l = 0; l < 4; l++) {
                const float* bv = sm + OFF_TOPB + (4*q + l)*128 + g*8;
                float ce = 0.f, ca = 0.f;
                #pragma unroll
                for (int j = 0; j < 8; j++) { ce += as[l][j]*bv[j]; ca += la[l][j]*bv[j]; }
                ce *= pe;
                sm[OFF_BUFA + (4*q + l)*128 + wt] = ce;
                acc += pe*ca + lsp[l]*ce;
            }
        }
        __syncthreads();
        // down lvl2 (16) -> eps of lvl3 roots
        #pragma unroll 1
        for (int rr = 0; rr < 4; rr++) {
            int k = rr*4 + q;
            float epsv = sm[OFF_BUFA + k*128 + wt];
            float pe = epsv / sm[OFF_TOPSB + k*128 + wt];
            int labu = tn[(5 + k)*7];
            acc += epsv * g_lbt[g*2048 + labu*8 + i];
            #pragma unroll
            for (int l = 0; l < 4; l++) {
                const float* bv = sm + OFF_BUFB + (4*k + l)*128 + g*8;
                float ce = 0.f, ca = 0.f;
                #pragma unroll
                for (int j = 0; j < 8; j++) { ce += as[l][j]*bv[j]; ca += la[l][j]*bv[j]; }
                ce *= pe;
                g_eps3[(4*k + l)*128 + wt] = ce;
                acc += pe*ca + lsp[l]*ce;
            }
        }
    }
    gbar();

    // ================= phase 3: subtree down =================
    // lvl3 down
    if (q == 0) {
        float eps3 = g_eps3[s*128 + wt];
        float pe = eps3 / sm[OFF_SBETA + wt];
        int lab3 = tn[(21 + s)*7];
        acc += eps3 * g_lbt[g*2048 + lab3*8 + i];
        #pragma unroll
        for (int l = 0; l < 4; l++) {
            const float* bv = sm + OFF_BETA + l*128 + g*8;
            float ce = 0.f, ca = 0.f;
            #pragma unroll
            for (int j = 0; j < 8; j++) { ce += as[l][j]*bv[j]; ca += la[l][j]*bv[j]; }
            ce *= pe;
            sm[OFF_BUFA + (16 + l)*128 + wt] = ce;
            acc += pe*ca + lsp[l]*ce;
        }
    }
    __syncthreads();
    // lvl4 down (4)
    {
        float epsv = sm[OFF_BUFA + (16 + q)*128 + wt];
        float pe = epsv / sm[OFF_SBETA + (1 + q)*128 + wt];
        int labu = tn[(85 + 4*s + q)*7];
        acc += epsv * g_lbt[g*2048 + labu*8 + i];
        #pragma unroll
        for (int l = 0; l < 4; l++) {
            const float* bv = sm + OFF_BETA + (4 + 4*q + l)*128 + g*8;
            float ce = 0.f, ca = 0.f;
            #pragma unroll
            for (int j = 0; j < 8; j++) { ce += as[l][j]*bv[j]; ca += la[l][j]*bv[j]; }
            ce *= pe;
            sm[OFF_BUFA + (4*q + l)*128 + wt] = ce;
            acc += pe*ca + lsp[l]*ce;
        }
    }
    __syncthreads();
    // lvl5 down (16)
    #pragma unroll 1
    for (int rr = 0; rr < 4; rr++) {
        int k = rr*4 + q;
        float epsv = sm[OFF_BUFA + k*128 + wt];
        float pe = epsv / sm[OFF_SBETA + (5 + k)*128 + wt];
        int labu = tn[(341 + 16*s + k)*7];
        acc += epsv * g_lbt[g*2048 + labu*8 + i];
        #pragma unroll
        for (int l = 0; l < 4; l++) {
            const float* bv = sm + OFF_BETA + (20 + 4*k + l)*128 + g*8;
            float ce = 0.f, ca = 0.f;
            #pragma unroll
            for (int j = 0; j < 8; j++) { ce += as[l][j]*bv[j]; ca += la[l][j]*bv[j]; }
            ce *= pe;
            sm[OFF_BUFB + (4*k + l)*128 + wt] = ce;
            acc += pe*ca + lsp[l]*ce;
        }
    }
    __syncthreads();
    // lvl6 down (64): leaf children inline, accumulate leaf b_lh + pi_lh + sp_lh
    #pragma unroll 1
    for (int rr = 0; rr < 16; rr++) {
        int k = rr*4 + q;
        int u6 = 1365 + 64*s + k;
        int Lb = 4*u6 + 1;
        int pre = (lane < 4) ? tn[(Lb + lane)*7] : (lane == 4 ? tn[u6*7] : 0);
        float epsv = sm[OFF_BUFB + k*128 + wt];
        float pe = epsv / sm[OFF_SBETA + (21 + k)*128 + wt];
        int labu = __shfl_sync(0xffffffffu, pre, 4);
        acc += epsv * g_lbt[g*2048 + labu*8 + i];
        #pragma unroll
        for (int l = 0; l < 4; l++) {
            int labl = __shfl_sync(0xffffffffu, pre, l);
            float lb = g_pit[g*32 + l*8 + i] * g_bt[g*2048 + labl*8 + i];
            lb /= sum8(lb);
            float ce = 0.f, ca = 0.f;
            #pragma unroll
            for (int j = 0; j < 8; j++) {
                float v = __shfl_sync(0xffffffffu, lb, j, 8);
                ce += as[l][j]*v; ca += la[l][j]*v;
            }
            ce *= pe;
            float w = lsp[l] + g_lbt[g*2048 + labl*8 + i] + g_lpit[g*32 + l*8 + i];
            acc += pe*ca + w*ce;
        }
    }

    // ================= reduce =================
    acc = sum8(acc);
    if (i == 0) sm[OFF_RED + q*16 + g] = acc;
    __syncthreads();
    if (tid < 16) {
        float p = sm[OFF_RED + tid] + sm[OFF_RED + 16 + tid]
                + sm[OFF_RED + 32 + tid] + sm[OFF_RED + 48 + tid];
        atomicAdd(&g_accum[tid], p);
    }
    gbar();
    if (s == 0 && tid < 16) out[tid] = g_accum[tid];
}

// ---------------------------------------------------------------------------
extern "C" void kernel_launch(void* const* d_in, const int* in_sizes, int n_in,
                              void* d_out, int out_size)
{
    const int*   tn = (const int*)  d_in[0];
    const float* a  = (const float*)d_in[2];
    const float* b  = (const float*)d_in[3];
    const float* pi = (const float*)d_in[4];
    const float* sp = (const float*)d_in[5];
    float* out = (float*)d_out;

    cudaFuncSetAttribute(main_kernel,
                         cudaFuncAttributeMaxDynamicSharedMemorySize,
                         SMEM_FLOATS * 4);
    main_kernel<<<64, 512, SMEM_FLOATS * 4>>>(tn, a, b, pi, sp, out);
}

// round 5
// speedup vs baseline: 2.2490x; 1.5277x over previous
#include <cuda_runtime.h>

// ---------------------------------------------------------------------------
// BottomUpHTMM — complete 4-ary tree depth 7, single persistent kernel.
// 64 blocks (one per level-3 subtree), 512 threads (4 groups of 128 = (g,c)).
// Leaf children folded into precomputed tables up_tab/dn_tab[(pos,label)][g*8+c].
// ---------------------------------------------------------------------------

#define GC 128

// tables
__device__ float g_asp [4096];      // a_sp[g][i][l][j]   (wt=g*8+i -> wt*32+l*8+j)
__device__ float g_loga[4096];      // log sm_a
__device__ float g_bt  [16*256*8];  // sm_b[g][m][c]
__device__ float g_lbt [16*256*8];
__device__ float g_pit [512];       // sm_pi[g][pos][c]
__device__ float g_lpit[512];
__device__ float g_lsp [64];        // log sm_sp[g][l]

// leaf contribution tables: index (l*256+lab)*128 + wt
__device__ float g_uptab[1024 * GC];
__device__ float g_dntab[1024 * GC];

// cross-block state
__device__ float g_beta3[64 * GC];
__device__ float g_eps3 [64 * GC];
__device__ float g_accum[16];

// grid barrier
__device__ unsigned g_cnt = 0;
__device__ unsigned g_gen = 0;

// shared-memory layout (floats)
#define OFF_BETA   0        // 84*128: lvl4 k:0..3, lvl5 4+k:4..19, lvl6 20+k:20..83
#define OFF_SBETA  10752    // 85*128: lvl3:0, lvl4 1+k, lvl5 5+k, lvl6 21+k
#define OFF_BUFA   21632    // 20*128
#define OFF_BUFB   24192    // 64*128
#define OFF_TOPB   32384    // 20*128: lvl2 0..15, lvl1 16..19 (block 0 only)
#define OFF_TOPSB  34944    // 20*128
#define OFF_EPS1   37504    // 4*128
#define OFF_RED    38016    // 64
#define SMEM_FLOATS 38080   // 152320 bytes

__device__ __forceinline__ float sum8(float v) {
    v += __shfl_xor_sync(0xffffffffu, v, 4);
    v += __shfl_xor_sync(0xffffffffu, v, 2);
    v += __shfl_xor_sync(0xffffffffu, v, 1);
    return v;
}

__device__ __forceinline__ void load_tab(const float* __restrict__ base, int wt,
                                         float (&r)[4][8]) {
    const float4* p = (const float4*)(base + wt * 32);
    #pragma unroll
    for (int l = 0; l < 4; l++) {
        float4 a = p[2*l], b = p[2*l + 1];
        r[l][0]=a.x; r[l][1]=a.y; r[l][2]=a.z; r[l][3]=a.w;
        r[l][4]=b.x; r[l][5]=b.y; r[l][6]=b.z; r[l][7]=b.w;
    }
}

// sense-reversing grid barrier for exactly 64 blocks
__device__ __forceinline__ void gbar() {
    __syncthreads();
    if (threadIdx.x == 0) {
        __threadfence();
        unsigned gen = atomicAdd(&g_gen, 0u);
        unsigned old = atomicAdd(&g_cnt, 1u);
        if (old == 63u) {
            atomicExch(&g_cnt, 0u);
            __threadfence();
            atomicAdd(&g_gen, 1u);
        } else {
            while (atomicAdd(&g_gen, 0u) == gen) __nanosleep(64);
        }
        __threadfence();
    }
    __syncthreads();
}

__device__ __forceinline__ float dot_up(const float* __restrict__ cb0,
                                        const float (&as)[4][8], int g) {
    float sb = 0.f;
    #pragma unroll
    for (int l = 0; l < 4; l++) {
        const float* bv = cb0 + l*128 + g*8;
        #pragma unroll
        for (int j = 0; j < 8; j++) sb += as[l][j] * bv[j];
    }
    return sb;
}

__global__ void __launch_bounds__(512, 1)
main_kernel(const int* __restrict__ tn,
            const float* __restrict__ a,
            const float* __restrict__ b,
            const float* __restrict__ pi,
            const float* __restrict__ sp,
            float* __restrict__ out)
{
    extern __shared__ float sm[];
    const int tid = threadIdx.x, s = blockIdx.x;
    const int q = tid >> 7, wt = tid & 127, g = wt >> 3, i = wt & 7;

    // ================= phase 0a: softmax prep =================
    if (s < 16) {
        if (tid < 256) {
            int w = tid >> 5, ln = tid & 31;
            const float* bp = b + (s*8 + w) * 256;
            float mx = -1e30f;
            for (int m = ln; m < 256; m += 32) mx = fmaxf(mx, bp[m]);
            #pragma unroll
            for (int o = 16; o; o >>= 1) mx = fmaxf(mx, __shfl_xor_sync(0xffffffffu, mx, o));
            float ssum = 0.f;
            for (int m = ln; m < 256; m += 32) ssum += expf(bp[m] - mx);
            #pragma unroll
            for (int o = 16; o; o >>= 1) ssum += __shfl_xor_sync(0xffffffffu, ssum, o);
            float inv = 1.f / ssum, ls = logf(ssum);
            for (int m = ln; m < 256; m += 32) {
                float e = bp[m] - mx;
                g_bt [s*2048 + m*8 + w] = expf(e) * inv;
                g_lbt[s*2048 + m*8 + w] = e - ls;
            }
        }
    } else if (s == 16) {
        float* s_sp = sm + OFF_RED;   // 64 floats scratch
        if (tid < 16) {
            float v[4]; float mx = -1e30f;
            #pragma unroll
            for (int l = 0; l < 4; l++) { v[l] = sp[tid*4 + l]; mx = fmaxf(mx, v[l]); }
            float su = 0.f;
            #pragma unroll
            for (int l = 0; l < 4; l++) { v[l] = expf(v[l] - mx); su += v[l]; }
            float inv = 1.f / su;
            #pragma unroll
            for (int l = 0; l < 4; l++) {
                float smv = v[l] * inv;
                s_sp[tid*4 + l]  = smv;
                g_lsp[tid*4 + l] = logf(smv);
            }
        }
        if (tid < 64) {
            int gg = tid >> 2, l = tid & 3;
            float v[8]; float mx = -1e30f;
            #pragma unroll
            for (int c = 0; c < 8; c++) { v[c] = pi[gg*32 + c*4 + l]; mx = fmaxf(mx, v[c]); }
            float su = 0.f;
            #pragma unroll
            for (int c = 0; c < 8; c++) { v[c] = expf(v[c] - mx); su += v[c]; }
            float inv = 1.f / su, ls = logf(su);
            #pragma unroll
            for (int c = 0; c < 8; c++) {
                g_pit [gg*32 + l*8 + c] = v[c] * inv;
                g_lpit[gg*32 + l*8 + c] = logf(v[c]) - ls;
            }
        }
        __syncthreads();
        {   // sm_a: 512 (g,j,l) groups, one per thread
            int grp = tid;
            int gg = grp >> 5, j = (grp >> 2) & 7, l = grp & 3;
            float v[8]; float mx = -1e30f;
            #pragma unroll
            for (int ii = 0; ii < 8; ii++) {
                v[ii] = a[gg*256 + ii*32 + j*4 + l];
                mx = fmaxf(mx, v[ii]);
            }
            float su = 0.f;
            #pragma unroll
            for (int ii = 0; ii < 8; ii++) { v[ii] = expf(v[ii] - mx); su += v[ii]; }
            float inv = 1.f / su, ls = logf(su);
            float spv = s_sp[gg*4 + l];
            #pragma unroll
            for (int ii = 0; ii < 8; ii++) {
                int idx = ((gg*8 + ii)*4 + l)*8 + j;
                g_asp [idx] = v[ii] * inv * spv;
                g_loga[idx] = logf(v[ii]) - ls;
            }
        }
    } else if (s == 17) {
        if (tid < 16) g_accum[tid] = 0.f;
    }
    gbar();

    // constant tables in registers
    float as[4][8], la[4][8];
    load_tab(g_asp, wt, as);
    load_tab(g_loga, wt, la);
    #pragma unroll
    for (int l = 0; l < 4; l++)
        #pragma unroll
        for (int j = 0; j < 8; j++) la[l][j] *= as[l][j];
    float lsp[4];
    #pragma unroll
    for (int l = 0; l < 4; l++) lsp[l] = g_lsp[g*4 + l];

    // ================= phase 0b: leaf tables =================
    // t = (l,lab) in 0..1023; group (s,q) handles t = s*4+q + 256*r
    #pragma unroll
    for (int r = 0; r < 4; r++) {
        int t = (s*4 + q) + 256*r;
        int l = t >> 8, lab = t & 255;
        float lb = g_pit[g*32 + l*8 + i] * g_bt[g*2048 + lab*8 + i];
        lb /= sum8(lb);
        float ce = 0.f, ca = 0.f;
        #pragma unroll
        for (int j = 0; j < 8; j++) {
            float v = __shfl_sync(0xffffffffu, lb, j, 8);
            ce += as[l][j]*v; ca += la[l][j]*v;
        }
        float w = lsp[l] + g_lpit[g*32 + l*8 + i] + g_lbt[g*2048 + lab*8 + i];
        g_uptab[t*128 + wt] = ce;
        g_dntab[t*128 + wt] = ca + w*ce;
    }
    gbar();

    // ================= phase 1: subtree up =================
    // lvl6 (64 nodes/subtree): leaf children via up_tab
    #pragma unroll 2
    for (int rr = 0; rr < 16; rr++) {
        int k = rr*4 + q;
        int u6 = 1365 + 64*s + k;
        int Lb = 4*u6 + 1;
        int lab0 = tn[Lb*7], lab1 = tn[(Lb+1)*7], lab2 = tn[(Lb+2)*7], lab3 = tn[(Lb+3)*7];
        int labu = tn[u6*7];
        float sb = g_uptab[(0*256 + lab0)*128 + wt]
                 + g_uptab[(1*256 + lab1)*128 + wt]
                 + g_uptab[(2*256 + lab2)*128 + wt]
                 + g_uptab[(3*256 + lab3)*128 + wt];
        float tmp = g_bt[g*2048 + labu*8 + i] * sb;
        float ts = sum8(tmp);
        sm[OFF_BETA  + (20 + k)*128 + wt] = tmp / ts;
        sm[OFF_SBETA + (21 + k)*128 + wt] = sb;
    }
    __syncthreads();
    // lvl5 (16)
    #pragma unroll 2
    for (int rr = 0; rr < 4; rr++) {
        int k = rr*4 + q;
        float sb = dot_up(sm + OFF_BETA + (20 + 4*k)*128, as, g);
        int labu = tn[(341 + 16*s + k)*7];
        float tmp = g_bt[g*2048 + labu*8 + i] * sb;
        float ts = sum8(tmp);
        sm[OFF_BETA  + (4 + k)*128 + wt] = tmp / ts;
        sm[OFF_SBETA + (5 + k)*128 + wt] = sb;
    }
    __syncthreads();
    // lvl4 (4)
    {
        float sb = dot_up(sm + OFF_BETA + (4 + 4*q)*128, as, g);
        int labu = tn[(85 + 4*s + q)*7];
        float tmp = g_bt[g*2048 + labu*8 + i] * sb;
        float ts = sum8(tmp);
        sm[OFF_BETA  + q*128 + wt]       = tmp / ts;
        sm[OFF_SBETA + (1 + q)*128 + wt] = sb;
    }
    __syncthreads();
    // lvl3 (subtree root)
    if (q == 0) {
        float sb = dot_up(sm + OFF_BETA, as, g);
        int labu = tn[(21 + s)*7];
        float tmp = g_bt[g*2048 + labu*8 + i] * sb;
        float ts = sum8(tmp);
        g_beta3[s*128 + wt] = tmp / ts;
        sm[OFF_SBETA + wt] = sb;
    }
    gbar();

    // ================= phase 2: top levels (block 0 only) =================
    float acc = 0.f;
    if (s == 0) {
        for (int idx = tid; idx < 64*128; idx += 512)
            sm[OFF_BUFB + idx] = g_beta3[idx];
        __syncthreads();
        // up lvl2 (16)
        #pragma unroll 1
        for (int rr = 0; rr < 4; rr++) {
            int k = rr*4 + q;
            float sb = dot_up(sm + OFF_BUFB + 4*k*128, as, g);
            int labu = tn[(5 + k)*7];
            float tmp = g_bt[g*2048 + labu*8 + i] * sb;
            float ts = sum8(tmp);
            sm[OFF_TOPB  + k*128 + wt] = tmp / ts;
            sm[OFF_TOPSB + k*128 + wt] = sb;
        }
        __syncthreads();
        // up lvl1 (4)
        {
            float sb = dot_up(sm + OFF_TOPB + 4*q*128, as, g);
            int labu = tn[(1 + q)*7];
            float tmp = g_bt[g*2048 + labu*8 + i] * sb;
            float ts = sum8(tmp);
            sm[OFF_TOPB  + (16 + q)*128 + wt] = tmp / ts;
            sm[OFF_TOPSB + (16 + q)*128 + wt] = sb;
        }
        __syncthreads();
        // lvl0 up+down fused
        if (q == 0) {
            float sb = dot_up(sm + OFF_TOPB + 16*128, as, g);
            int lab0 = tn[0];
            float tmp = g_bt[g*2048 + lab0*8 + i] * sb;
            float ts = sum8(tmp);
            float betar = tmp / ts;
            float pe = betar / sb;
            acc += betar * g_lbt[g*2048 + lab0*8 + i];
            #pragma unroll
            for (int l = 0; l < 4; l++) {
                const float* bv = sm + OFF_TOPB + (16 + l)*128 + g*8;
                float ce = 0.f, ca = 0.f;
                #pragma unroll
                for (int j = 0; j < 8; j++) { ce += as[l][j]*bv[j]; ca += la[l][j]*bv[j]; }
                ce *= pe;
                sm[OFF_EPS1 + l*128 + wt] = ce;
                acc += pe*ca + lsp[l]*ce;
            }
        }
        __syncthreads();
        // down lvl1 (4)
        {
            float epsv = sm[OFF_EPS1 + q*128 + wt];
            float pe = epsv / sm[OFF_TOPSB + (16 + q)*128 + wt];
            int labu = tn[(1 + q)*7];
            acc += epsv * g_lbt[g*2048 + labu*8 + i];
            #pragma unroll
            for (int l = 0; l < 4; l++) {
                const float* bv = sm + OFF_TOPB + (4*q + l)*128 + g*8;
                float ce = 0.f, ca = 0.f;
                #pragma unroll
                for (int j = 0; j < 8; j++) { ce += as[l][j]*bv[j]; ca += la[l][j]*bv[j]; }
                ce *= pe;
                sm[OFF_BUFA + (4*q + l)*128 + wt] = ce;
                acc += pe*ca + lsp[l]*ce;
            }
        }
        __syncthreads();
        // down lvl2 (16) -> eps of lvl3 roots
        #pragma unroll 1
        for (int rr = 0; rr < 4; rr++) {
            int k = rr*4 + q;
            float epsv = sm[OFF_BUFA + k*128 + wt];
            float pe = epsv / sm[OFF_TOPSB + k*128 + wt];
            int labu = tn[(5 + k)*7];
            acc += epsv * g_lbt[g*2048 + labu*8 + i];
            #pragma unroll
            for (int l = 0; l < 4; l++) {
                const float* bv = sm + OFF_BUFB + (4*k + l)*128 + g*8;
                float ce = 0.f, ca = 0.f;
                #pragma unroll
                for (int j = 0; j < 8; j++) { ce += as[l][j]*bv[j]; ca += la[l][j]*bv[j]; }
                ce *= pe;
                g_eps3[(4*k + l)*128 + wt] = ce;
                acc += pe*ca + lsp[l]*ce;
            }
        }
    }
    gbar();

    // ================= phase 3: subtree down =================
    // lvl3 down
    if (q == 0) {
        float eps3 = g_eps3[s*128 + wt];
        float pe = eps3 / sm[OFF_SBETA + wt];
        int lab3 = tn[(21 + s)*7];
        acc += eps3 * g_lbt[g*2048 + lab3*8 + i];
        #pragma unroll
        for (int l = 0; l < 4; l++) {
            const float* bv = sm + OFF_BETA + l*128 + g*8;
            float ce = 0.f, ca = 0.f;
            #pragma unroll
            for (int j = 0; j < 8; j++) { ce += as[l][j]*bv[j]; ca += la[l][j]*bv[j]; }
            ce *= pe;
            sm[OFF_BUFA + (16 + l)*128 + wt] = ce;
            acc += pe*ca + lsp[l]*ce;
        }
    }
    __syncthreads();
    // lvl4 down (4)
    {
        float epsv = sm[OFF_BUFA + (16 + q)*128 + wt];
        float pe = epsv / sm[OFF_SBETA + (1 + q)*128 + wt];
        int labu = tn[(85 + 4*s + q)*7];
        acc += epsv * g_lbt[g*2048 + labu*8 + i];
        #pragma unroll
        for (int l = 0; l < 4; l++) {
            const float* bv = sm + OFF_BETA + (4 + 4*q + l)*128 + g*8;
            float ce = 0.f, ca = 0.f;
            #pragma unroll
            for (int j = 0; j < 8; j++) { ce += as[l][j]*bv[j]; ca += la[l][j]*bv[j]; }
            ce *= pe;
            sm[OFF_BUFA + (4*q + l)*128 + wt] = ce;
            acc += pe*ca + lsp[l]*ce;
        }
    }
    __syncthreads();
    // lvl5 down (16)
    #pragma unroll 1
    for (int rr = 0; rr < 4; rr++) {
        int k = rr*4 + q;
        float epsv = sm[OFF_BUFA + k*128 + wt];
        float pe = epsv / sm[OFF_SBETA + (5 + k)*128 + wt];
        int labu = tn[(341 + 16*s + k)*7];
        acc += epsv * g_lbt[g*2048 + labu*8 + i];
        #pragma unroll
        for (int l = 0; l < 4; l++) {
            const float* bv = sm + OFF_BETA + (20 + 4*k + l)*128 + g*8;
            float ce = 0.f, ca = 0.f;
            #pragma unroll
            for (int j = 0; j < 8; j++) { ce += as[l][j]*bv[j]; ca += la[l][j]*bv[j]; }
            ce *= pe;
            sm[OFF_BUFB + (4*k + l)*128 + wt] = ce;
            acc += pe*ca + lsp[l]*ce;
        }
    }
    __syncthreads();
    // lvl6 down (64): leaf children via dn_tab
    #pragma unroll 2
    for (int rr = 0; rr < 16; rr++) {
        int k = rr*4 + q;
        int u6 = 1365 + 64*s + k;
        int Lb = 4*u6 + 1;
        int lab0 = tn[Lb*7], lab1 = tn[(Lb+1)*7], lab2 = tn[(Lb+2)*7], lab3 = tn[(Lb+3)*7];
        int labu = tn[u6*7];
        float epsv = sm[OFF_BUFB + k*128 + wt];
        float pe = epsv / sm[OFF_SBETA + (21 + k)*128 + wt];
        acc += epsv * g_lbt[g*2048 + labu*8 + i];
        float d = g_dntab[(0*256 + lab0)*128 + wt]
                + g_dntab[(1*256 + lab1)*128 + wt]
                + g_dntab[(2*256 + lab2)*128 + wt]
                + g_dntab[(3*256 + lab3)*128 + wt];
        acc += pe * d;
    }

    // ================= reduce =================
    acc = sum8(acc);
    if (i == 0) sm[OFF_RED + q*16 + g] = acc;
    __syncthreads();
    if (tid < 16) {
        float p = sm[OFF_RED + tid] + sm[OFF_RED + 16 + tid]
                + sm[OFF_RED + 32 + tid] + sm[OFF_RED + 48 + tid];
        atomicAdd(&g_accum[tid], p);
    }
    gbar();
    if (s == 0 && tid < 16) out[tid] = g_accum[tid];
}

// ---------------------------------------------------------------------------
extern "C" void kernel_launch(void* const* d_in, const int* in_sizes, int n_in,
                              void* d_out, int out_size)
{
    const int*   tn = (const int*)  d_in[0];
    const float* a  = (const float*)d_in[2];
    const float* b  = (const float*)d_in[3];
    const float* pi = (const float*)d_in[4];
    const float* sp = (const float*)d_in[5];
    float* out = (float*)d_out;

    cudaFuncSetAttribute(main_kernel,
                         cudaFuncAttributeMaxDynamicSharedMemorySize,
                         SMEM_FLOATS * 4);
    main_kernel<<<64, 512, SMEM_FLOATS * 4>>>(tn, a, b, pi, sp, out);
}

// round 6
// speedup vs baseline: 2.4330x; 1.0818x over previous
#include <cuda_runtime.h>

// ---------------------------------------------------------------------------
// BottomUpHTMM — complete 4-ary tree depth 7, single persistent kernel.
// 128 blocks x 512 threads. Each block owns TWO level-4 subtrees
// (lvl4 root + 4 lvl5 + 16 lvl6 + 64 leaves each). Level-3 nodes distributed
// over 64 blocks; lvl2/1/0 on block 0. Leaf children folded into precomputed
// tables up_tab/dn_tab[(pos,label)][g*8+c]. Software grid barrier (128 blocks
// co-resident: 1 block/SM by smem/regs, grid <= #SMs).
// ---------------------------------------------------------------------------

#define GC    128
#define NBLK  128

// tables
__device__ float g_asp [4096];      // a_sp[g][i][l][j]   (wt=g*8+i -> wt*32+l*8+j)
__device__ float g_loga[4096];      // log sm_a
__device__ float g_bt  [16*256*8];  // sm_b[g][m][c]
__device__ float g_lbt [16*256*8];
__device__ float g_pit [512];       // sm_pi[g][pos][c]
__device__ float g_lpit[512];
__device__ float g_lsp [64];        // log sm_sp[g][l]

// leaf contribution tables: index (l*256+lab)*128 + wt
__device__ float g_uptab[1024 * GC];
__device__ float g_dntab[1024 * GC];

// cross-block state
__device__ float g_beta4 [256 * GC];
__device__ float g_eps4  [256 * GC];
__device__ float g_beta3 [64 * GC];
__device__ float g_sbeta3[64 * GC];
__device__ float g_eps3  [64 * GC];
__device__ float g_accum [16];

// grid barrier
__device__ unsigned g_cnt = 0;
__device__ unsigned g_gen = 0;

// shared-memory layout (floats)
#define OFF_B6    0        // 32 rows: lvl6 beta (k = local 0..31)
#define OFF_B5    4096     // 8 rows:  lvl5 beta
#define OFF_S6    5120     // 32 rows: lvl6 sbeta
#define OFF_S5    9216     // 8 rows:  lvl5 sbeta
#define OFF_S4    10240    // 2 rows:  lvl4 sbeta
#define OFF_E5    10496    // 8 rows:  lvl5 eps
#define OFF_E6    11520    // 32 rows: lvl6 eps
#define OFF_RED   15616    // 64
#define OFF_TOP   15680    // 64 rows: lvl3 betas (block 0, phase 2)
#define OFF_TOPB  23872    // 20 rows: lvl2 beta 0..15, lvl1 beta 16..19
#define OFF_TOPSB 26432    // 20 rows
#define OFF_EPS1  28992    // 4 rows
#define OFF_EPS2  29504    // 16 rows
#define SMEM_FLOATS 31552  // 126208 bytes

__device__ __forceinline__ float sum8(float v) {
    v += __shfl_xor_sync(0xffffffffu, v, 4);
    v += __shfl_xor_sync(0xffffffffu, v, 2);
    v += __shfl_xor_sync(0xffffffffu, v, 1);
    return v;
}

__device__ __forceinline__ void load_tab(const float* __restrict__ base, int wt,
                                         float (&r)[4][8]) {
    const float4* p = (const float4*)(base + wt * 32);
    #pragma unroll
    for (int l = 0; l < 4; l++) {
        float4 a = p[2*l], b = p[2*l + 1];
        r[l][0]=a.x; r[l][1]=a.y; r[l][2]=a.z; r[l][3]=a.w;
        r[l][4]=b.x; r[l][5]=b.y; r[l][6]=b.z; r[l][7]=b.w;
    }
}

// sense-reversing grid barrier for exactly NBLK blocks
__device__ __forceinline__ void gbar() {
    __syncthreads();
    if (threadIdx.x == 0) {
        __threadfence();
        unsigned gen = *(volatile unsigned*)&g_gen;
        unsigned old = atomicAdd(&g_cnt, 1u);
        if (old == NBLK - 1u) {
            g_cnt = 0u;
            __threadfence();
            atomicAdd(&g_gen, 1u);
        } else {
            while (*(volatile unsigned*)&g_gen == gen) __nanosleep(32);
        }
        __threadfence();
    }
    __syncthreads();
}

__device__ __forceinline__ float dot_up(const float* __restrict__ cb0,
                                        const float (&as)[4][8], int g) {
    float sb = 0.f;
    #pragma unroll
    for (int l = 0; l < 4; l++) {
        const float* bv = cb0 + l*128 + g*8;
        #pragma unroll
        for (int j = 0; j < 8; j++) sb += as[l][j] * bv[j];
    }
    return sb;
}

__global__ void __launch_bounds__(512, 1)
main_kernel(const int* __restrict__ tn,
            const float* __restrict__ a,
            const float* __restrict__ b,
            const float* __restrict__ pi,
            const float* __restrict__ sp,
            float* __restrict__ out)
{
    extern __shared__ float sm[];
    const int tid = threadIdx.x, s = blockIdx.x;
    const int q = tid >> 7, wt = tid & 127, g = wt >> 3, i = wt & 7;

    // ================= phase 0a: softmax prep =================
    if (s < 16) {
        if (tid < 256) {
            int w = tid >> 5, ln = tid & 31;
            const float* bp = b + (s*8 + w) * 256;
            float mx = -1e30f;
            for (int m = ln; m < 256; m += 32) mx = fmaxf(mx, bp[m]);
            #pragma unroll
            for (int o = 16; o; o >>= 1) mx = fmaxf(mx, __shfl_xor_sync(0xffffffffu, mx, o));
            float ssum = 0.f;
            for (int m = ln; m < 256; m += 32) ssum += expf(bp[m] - mx);
            #pragma unroll
            for (int o = 16; o; o >>= 1) ssum += __shfl_xor_sync(0xffffffffu, ssum, o);
            float inv = 1.f / ssum, ls = logf(ssum);
            for (int m = ln; m < 256; m += 32) {
                float e = bp[m] - mx;
                g_bt [s*2048 + m*8 + w] = expf(e) * inv;
                g_lbt[s*2048 + m*8 + w] = e - ls;
            }
        }
    } else if (s == 16) {
        float* s_sp = sm + OFF_RED;   // scratch
        if (tid < 16) {
            float v[4]; float mx = -1e30f;
            #pragma unroll
            for (int l = 0; l < 4; l++) { v[l] = sp[tid*4 + l]; mx = fmaxf(mx, v[l]); }
            float su = 0.f;
            #pragma unroll
            for (int l = 0; l < 4; l++) { v[l] = expf(v[l] - mx); su += v[l]; }
            float inv = 1.f / su;
            #pragma unroll
            for (int l = 0; l < 4; l++) {
                float smv = v[l] * inv;
                s_sp[tid*4 + l]  = smv;
                g_lsp[tid*4 + l] = logf(smv);
            }
        }
        if (tid < 64) {
            int gg = tid >> 2, l = tid & 3;
            float v[8]; float mx = -1e30f;
            #pragma unroll
            for (int c = 0; c < 8; c++) { v[c] = pi[gg*32 + c*4 + l]; mx = fmaxf(mx, v[c]); }
            float su = 0.f;
            #pragma unroll
            for (int c = 0; c < 8; c++) { v[c] = expf(v[c] - mx); su += v[c]; }
            float inv = 1.f / su, ls = logf(su);
            #pragma unroll
            for (int c = 0; c < 8; c++) {
                g_pit [gg*32 + l*8 + c] = v[c] * inv;
                g_lpit[gg*32 + l*8 + c] = logf(v[c]) - ls;
            }
        }
        __syncthreads();
        {   // sm_a: 512 (g,j,l) groups, one per thread
            int grp = tid;
            int gg = grp >> 5, j = (grp >> 2) & 7, l = grp & 3;
            float v[8]; float mx = -1e30f;
            #pragma unroll
            for (int ii = 0; ii < 8; ii++) {
                v[ii] = a[gg*256 + ii*32 + j*4 + l];
                mx = fmaxf(mx, v[ii]);
            }
            float su = 0.f;
            #pragma unroll
            for (int ii = 0; ii < 8; ii++) { v[ii] = expf(v[ii] - mx); su += v[ii]; }
            float inv = 1.f / su, ls = logf(su);
            float spv = s_sp[gg*4 + l];
            #pragma unroll
            for (int ii = 0; ii < 8; ii++) {
                int idx = ((gg*8 + ii)*4 + l)*8 + j;
                g_asp [idx] = v[ii] * inv * spv;
                g_loga[idx] = logf(v[ii]) - ls;
            }
        }
    } else if (s == 17) {
        if (tid < 16) g_accum[tid] = 0.f;
    }
    gbar();

    // constant tables in registers
    float as[4][8], la[4][8];
    load_tab(g_asp, wt, as);
    load_tab(g_loga, wt, la);
    #pragma unroll
    for (int l = 0; l < 4; l++)
        #pragma unroll
        for (int j = 0; j < 8; j++) la[l][j] *= as[l][j];
    float lsp[4];
    #pragma unroll
    for (int l = 0; l < 4; l++) lsp[l] = g_lsp[g*4 + l];

    // ================= phase 0b: leaf tables =================
    // t = (l,lab) in 0..1023; group (s,q) handles t = s*4+q + 512*r
    #pragma unroll
    for (int r = 0; r < 2; r++) {
        int t = (s*4 + q) + 512*r;
        int l = t >> 8, lab = t & 255;
        float lb = g_pit[g*32 + l*8 + i] * g_bt[g*2048 + lab*8 + i];
        lb /= sum8(lb);
        float ce = 0.f, ca = 0.f;
        #pragma unroll
        for (int j = 0; j < 8; j++) {
            float v = __shfl_sync(0xffffffffu, lb, j, 8);
            ce += as[l][j]*v; ca += la[l][j]*v;
        }
        float w = lsp[l] + g_lpit[g*32 + l*8 + i] + g_lbt[g*2048 + lab*8 + i];
        g_uptab[t*128 + wt] = ce;
        g_dntab[t*128 + wt] = ca + w*ce;
    }
    gbar();

    // ================= phase 1: pair-of-subtrees up =================
    // lvl6 (32 nodes/block): leaf children via up_tab. t6 = 32*s + k
    #pragma unroll 2
    for (int rr = 0; rr < 8; rr++) {
        int k = rr*4 + q;
        int u6 = 1365 + 32*s + k;
        int Lb = 4*u6 + 1;
        int lab0 = tn[Lb*7], lab1 = tn[(Lb+1)*7], lab2 = tn[(Lb+2)*7], lab3 = tn[(Lb+3)*7];
        int labu = tn[u6*7];
        float sb = g_uptab[(0*256 + lab0)*128 + wt]
                 + g_uptab[(1*256 + lab1)*128 + wt]
                 + g_uptab[(2*256 + lab2)*128 + wt]
                 + g_uptab[(3*256 + lab3)*128 + wt];
        float tmp = g_bt[g*2048 + labu*8 + i] * sb;
        float ts = sum8(tmp);
        sm[OFF_B6 + k*128 + wt] = tmp / ts;
        sm[OFF_S6 + k*128 + wt] = sb;
    }
    __syncthreads();
    // lvl5 (8 nodes): t5 = 8*s + k, children rows 4k..4k+3
    #pragma unroll 2
    for (int rr = 0; rr < 2; rr++) {
        int k = rr*4 + q;
        float sb = dot_up(sm + OFF_B6 + 4*k*128, as, g);
        int labu = tn[(341 + 8*s + k)*7];
        float tmp = g_bt[g*2048 + labu*8 + i] * sb;
        float ts = sum8(tmp);
        sm[OFF_B5 + k*128 + wt] = tmp / ts;
        sm[OFF_S5 + k*128 + wt] = sb;
    }
    __syncthreads();
    // lvl4 (2 nodes): t4 = 2*s + q (q<2), children rows 4q..4q+3
    if (q < 2) {
        int t4 = 2*s + q;
        float sb = dot_up(sm + OFF_B5 + 4*q*128, as, g);
        int labu = tn[(85 + t4)*7];
        float tmp = g_bt[g*2048 + labu*8 + i] * sb;
        float ts = sum8(tmp);
        g_beta4[t4*128 + wt] = tmp / ts;
        sm[OFF_S4 + q*128 + wt] = sb;
    }
    gbar();

    // ================= phase 1b: lvl3 up (blocks 0..63, group 0) ==========
    if (s < 64 && q == 0) {
        float sb = 0.f;
        #pragma unroll
        for (int l = 0; l < 4; l++) {
            const float* bv = &g_beta4[(4*s + l)*128 + g*8];
            #pragma unroll
            for (int j = 0; j < 8; j++) sb += as[l][j] * bv[j];
        }
        int labu = tn[(21 + s)*7];
        float tmp = g_bt[g*2048 + labu*8 + i] * sb;
        float ts = sum8(tmp);
        g_beta3 [s*128 + wt] = tmp / ts;
        g_sbeta3[s*128 + wt] = sb;
    }
    gbar();

    // ================= phase 2: lvl2/1/0 up+down (block 0) =================
    float acc = 0.f;
    if (s == 0) {
        for (int idx = tid; idx < 64*128; idx += 512)
            sm[OFF_TOP + idx] = g_beta3[idx];
        __syncthreads();
        // up lvl2 (16)
        #pragma unroll 1
        for (int rr = 0; rr < 4; rr++) {
            int k = rr*4 + q;
            float sb = dot_up(sm + OFF_TOP + 4*k*128, as, g);
            int labu = tn[(5 + k)*7];
            float tmp = g_bt[g*2048 + labu*8 + i] * sb;
            float ts = sum8(tmp);
            sm[OFF_TOPB  + k*128 + wt] = tmp / ts;
            sm[OFF_TOPSB + k*128 + wt] = sb;
        }
        __syncthreads();
        // up lvl1 (4)
        {
            float sb = dot_up(sm + OFF_TOPB + 4*q*128, as, g);
            int labu = tn[(1 + q)*7];
            float tmp = g_bt[g*2048 + labu*8 + i] * sb;
            float ts = sum8(tmp);
            sm[OFF_TOPB  + (16 + q)*128 + wt] = tmp / ts;
            sm[OFF_TOPSB + (16 + q)*128 + wt] = sb;
        }
        __syncthreads();
        // lvl0 up+down fused (group 0)
        if (q == 0) {
            float sb = dot_up(sm + OFF_TOPB + 16*128, as, g);
            int lab0 = tn[0];
            float tmp = g_bt[g*2048 + lab0*8 + i] * sb;
            float ts = sum8(tmp);
            float betar = tmp / ts;
            float pe = betar / sb;
            acc += betar * g_lbt[g*2048 + lab0*8 + i];
            #pragma unroll
            for (int l = 0; l < 4; l++) {
                const float* bv = sm + OFF_TOPB + (16 + l)*128 + g*8;
                float ce = 0.f, ca = 0.f;
                #pragma unroll
                for (int j = 0; j < 8; j++) { ce += as[l][j]*bv[j]; ca += la[l][j]*bv[j]; }
                ce *= pe;
                sm[OFF_EPS1 + l*128 + wt] = ce;
                acc += pe*ca + lsp[l]*ce;
            }
        }
        __syncthreads();
        // down lvl1 (4)
        {
            float epsv = sm[OFF_EPS1 + q*128 + wt];
            float pe = epsv / sm[OFF_TOPSB + (16 + q)*128 + wt];
            int labu = tn[(1 + q)*7];
            acc += epsv * g_lbt[g*2048 + labu*8 + i];
            #pragma unroll
            for (int l = 0; l < 4; l++) {
                const float* bv = sm + OFF_TOPB + (4*q + l)*128 + g*8;
                float ce = 0.f, ca = 0.f;
                #pragma unroll
                for (int j = 0; j < 8; j++) { ce += as[l][j]*bv[j]; ca += la[l][j]*bv[j]; }
                ce *= pe;
                sm[OFF_EPS2 + (4*q + l)*128 + wt] = ce;
                acc += pe*ca + lsp[l]*ce;
            }
        }
        __syncthreads();
        // down lvl2 (16) -> eps of lvl3 nodes
        #pragma unroll 1
        for (int rr = 0; rr < 4; rr++) {
            int k = rr*4 + q;
            float epsv = sm[OFF_EPS2 + k*128 + wt];
            float pe = epsv / sm[OFF_TOPSB + k*128 + wt];
            int labu = tn[(5 + k)*7];
            acc += epsv * g_lbt[g*2048 + labu*8 + i];
            #pragma unroll
            for (int l = 0; l < 4; l++) {
                const float* bv = sm + OFF_TOP + (4*k + l)*128 + g*8;
                float ce = 0.f, ca = 0.f;
                #pragma unroll
                for (int j = 0; j < 8; j++) { ce += as[l][j]*bv[j]; ca += la[l][j]*bv[j]; }
                ce *= pe;
                g_eps3[(4*k + l)*128 + wt] = ce;
                acc += pe*ca + lsp[l]*ce;
            }
        }
    }
    gbar();

    // ================= phase 2b: lvl3 down (blocks 0..63, group 0) =========
    if (s < 64 && q == 0) {
        float eps3 = g_eps3[s*128 + wt];
        float pe = eps3 / g_sbeta3[s*128 + wt];
        int lab3 = tn[(21 + s)*7];
        acc += eps3 * g_lbt[g*2048 + lab3*8 + i];
        #pragma unroll
        for (int l = 0; l < 4; l++) {
            const float* bv = &g_beta4[(4*s + l)*128 + g*8];
            float ce = 0.f, ca = 0.f;
            #pragma unroll
            for (int j = 0; j < 8; j++) { ce += as[l][j]*bv[j]; ca += la[l][j]*bv[j]; }
            ce *= pe;
            g_eps4[(4*s + l)*128 + wt] = ce;
            acc += pe*ca + lsp[l]*ce;
        }
    }
    gbar();

    // ================= phase 3: pair-of-subtrees down =================
    // lvl4 down (2 nodes, q<2)
    if (q < 2) {
        int t4 = 2*s + q;
        float epsv = g_eps4[t4*128 + wt];
        float pe = epsv / sm[OFF_S4 + q*128 + wt];
        int labu = tn[(85 + t4)*7];
        acc += epsv * g_lbt[g*2048 + labu*8 + i];
        #pragma unroll
        for (int l = 0; l < 4; l++) {
            const float* bv = sm + OFF_B5 + (4*q + l)*128 + g*8;
            float ce = 0.f, ca = 0.f;
            #pragma unroll
            for (int j = 0; j < 8; j++) { ce += as[l][j]*bv[j]; ca += la[l][j]*bv[j]; }
            ce *= pe;
            sm[OFF_E5 + (4*q + l)*128 + wt] = ce;
            acc += pe*ca + lsp[l]*ce;
        }
    }
    __syncthreads();
    // lvl5 down (8)
    #pragma unroll 2
    for (int rr = 0; rr < 2; rr++) {
        int k = rr*4 + q;
        float epsv = sm[OFF_E5 + k*128 + wt];
        float pe = epsv / sm[OFF_S5 + k*128 + wt];
        int labu = tn[(341 + 8*s + k)*7];
        acc += epsv * g_lbt[g*2048 + labu*8 + i];
        #pragma unroll
        for (int l = 0; l < 4; l++) {
            const float* bv = sm + OFF_B6 + (4*k + l)*128 + g*8;
            float ce = 0.f, ca = 0.f;
            #pragma unroll
            for (int j = 0; j < 8; j++) { ce += as[l][j]*bv[j]; ca += la[l][j]*bv[j]; }
            ce *= pe;
            sm[OFF_E6 + (4*k + l)*128 + wt] = ce;
            acc += pe*ca + lsp[l]*ce;
        }
    }
    __syncthreads();
    // lvl6 down (32): leaf children via dn_tab
    #pragma unroll 2
    for (int rr = 0; rr < 8; rr++) {
        int k = rr*4 + q;
        int u6 = 1365 + 32*s + k;
        int Lb = 4*u6 + 1;
        int lab0 = tn[Lb*7], lab1 = tn[(Lb+1)*7], lab2 = tn[(Lb+2)*7], lab3 = tn[(Lb+3)*7];
        int labu = tn[u6*7];
        float epsv = sm[OFF_E6 + k*128 + wt];
        float pe = epsv / sm[OFF_S6 + k*128 + wt];
        acc += epsv * g_lbt[g*2048 + labu*8 + i];
        float d = g_dntab[(0*256 + lab0)*128 + wt]
                + g_dntab[(1*256 + lab1)*128 + wt]
                + g_dntab[(2*256 + lab2)*128 + wt]
                + g_dntab[(3*256 + lab3)*128 + wt];
        acc += pe * d;
    }

    // ================= reduce =================
    acc = sum8(acc);
    if (i == 0) sm[OFF_RED + q*16 + g] = acc;
    __syncthreads();
    if (tid < 16) {
        float p = sm[OFF_RED + tid] + sm[OFF_RED + 16 + tid]
                + sm[OFF_RED + 32 + tid] + sm[OFF_RED + 48 + tid];
        atomicAdd(&g_accum[tid], p);
    }
    gbar();
    if (s == 0 && tid < 16) out[tid] = g_accum[tid];
}

// ---------------------------------------------------------------------------
extern "C" void kernel_launch(void* const* d_in, const int* in_sizes, int n_in,
                              void* d_out, int out_size)
{
    const int*   tn = (const int*)  d_in[0];
    const float* a  = (const float*)d_in[2];
    const float* b  = (const float*)d_in[3];
    const float* pi = (const float*)d_in[4];
    const float* sp = (const float*)d_in[5];
    float* out = (float*)d_out;

    cudaFuncSetAttribute(main_kernel,
                         cudaFuncAttributeMaxDynamicSharedMemorySize,
                         SMEM_FLOATS * 4);
    main_kernel<<<NBLK, 512, SMEM_FLOATS * 4>>>(tn, a, b, pi, sp, out);
}

// round 7
// speedup vs baseline: 2.6222x; 1.0778x over previous
#include <cuda_runtime.h>

// ---------------------------------------------------------------------------
// BottomUpHTMM — complete 4-ary tree depth 7, single persistent kernel.
// 128 blocks x 512 threads; each block owns two level-4 subtrees.
// Fine-grained flag-based cross-block sync (only 2 full grid barriers).
// Labels staged to smem up-front. Leaf children folded into up/dn tables.
// ---------------------------------------------------------------------------

#define GC    128
#define NBLK  128

// tables
__device__ float g_asp [4096];      // a_sp[g][i][l][j]   (wt=g*8+i -> wt*32+l*8+j)
__device__ float g_loga[4096];      // log sm_a
__device__ float g_bt  [16*256*8];  // sm_b[g][m][c]
__device__ float g_lbt [16*256*8];
__device__ float g_pit [512];       // sm_pi[g][pos][c]
__device__ float g_lpit[512];
__device__ float g_lsp [64];        // log sm_sp[g][l]

// leaf contribution tables: index (l*256+lab)*128 + wt
__device__ float g_uptab[1024 * GC];
__device__ float g_dntab[1024 * GC];

// cross-block state
__device__ float g_beta4 [256 * GC];
__device__ float g_eps4  [256 * GC];
__device__ float g_beta3 [64 * GC];
__device__ float g_sbeta3[64 * GC];
__device__ float g_eps3  [64 * GC];
__device__ float g_accum [16];

// sync state
__device__ unsigned g_cnt = 0;
__device__ unsigned g_gen = 0;
__device__ unsigned g_f1[NBLK];     // beta4 of block s ready
__device__ unsigned g_c2;           // # lvl3 nodes done
__device__ unsigned g_f3;           // eps3 (all) ready
__device__ unsigned g_f4[64];       // eps4 of lvl3 node s' ready
__device__ unsigned g_cfin;         // finish ticket

// shared-memory layout (floats)
#define OFF_B6    0        // 32 rows: lvl6 beta
#define OFF_B5    4096     // 8 rows:  lvl5 beta
#define OFF_S6    5120     // 32 rows: lvl6 sbeta
#define OFF_S5    9216     // 8 rows:  lvl5 sbeta
#define OFF_S4    10240    // 2 rows:  lvl4 sbeta
#define OFF_E5    10496    // 8 rows:  lvl5 eps
#define OFF_E6    11520    // 32 rows: lvl6 eps
#define OFF_RED   15616    // 64
#define OFF_TOP   15680    // 64 rows: lvl3 betas (block 0)
#define OFF_TOPB  23872    // 20 rows: lvl2 beta 0..15, lvl1 16..19
#define OFF_TOPSB 26432    // 20 rows
#define OFF_EPS1  28992    // 4 rows
#define OFF_EPS2  29504    // 16 rows
#define OFF_LAB   31552    // 192 ints: leaf[128], l6[32], l5[8], l4[2], l3[1], top[21]
#define OFF_LAST  31744    // 1 (unsigned)
#define SMEM_FLOATS 31748  // ~127 KB

__device__ __forceinline__ float sum8(float v) {
    v += __shfl_xor_sync(0xffffffffu, v, 4);
    v += __shfl_xor_sync(0xffffffffu, v, 2);
    v += __shfl_xor_sync(0xffffffffu, v, 1);
    return v;
}

__device__ __forceinline__ void load_tab(const float* __restrict__ base, int wt,
                                         float (&r)[4][8]) {
    const float4* p = (const float4*)(base + wt * 32);
    #pragma unroll
    for (int l = 0; l < 4; l++) {
        float4 a = p[2*l], b = p[2*l + 1];
        r[l][0]=a.x; r[l][1]=a.y; r[l][2]=a.z; r[l][3]=a.w;
        r[l][4]=b.x; r[l][5]=b.y; r[l][6]=b.z; r[l][7]=b.w;
    }
}

// full grid barrier (NBLK blocks co-resident)
__device__ __forceinline__ void gbar() {
    __syncthreads();
    if (threadIdx.x == 0) {
        __threadfence();
        unsigned gen = *(volatile unsigned*)&g_gen;
        unsigned old = atomicAdd(&g_cnt, 1u);
        if (old == NBLK - 1u) {
            g_cnt = 0u;
            __threadfence();
            atomicAdd(&g_gen, 1u);
        } else {
            while (*(volatile unsigned*)&g_gen == gen) {}
        }
        __threadfence();
    }
    __syncthreads();
}

__device__ __forceinline__ float dot_up(const float* __restrict__ cb0,
                                        const float (&as)[4][8], int g) {
    float sb = 0.f;
    #pragma unroll
    for (int l = 0; l < 4; l++) {
        const float* bv = cb0 + l*128 + g*8;
        #pragma unroll
        for (int j = 0; j < 8; j++) sb += as[l][j] * bv[j];
    }
    return sb;
}

__global__ void __launch_bounds__(512, 1)
main_kernel(const int* __restrict__ tn,
            const float* __restrict__ a,
            const float* __restrict__ b,
            const float* __restrict__ pi,
            const float* __restrict__ sp,
            float* __restrict__ out)
{
    extern __shared__ float sm[];
    const int tid = threadIdx.x, s = blockIdx.x;
    const int q = tid >> 7, wt = tid & 127, g = wt >> 3, i = wt & 7;
    int* slab = (int*)(sm + OFF_LAB);

    // ---- stage labels (all blocks; overlaps with prep + barriers) ----
    if (tid < 192) {
        int idx = tid, node;
        if      (idx < 128) node = 5461 + 128*s + idx;
        else if (idx < 160) node = 1365 + 32*s + (idx - 128);
        else if (idx < 168) node = 341 + 8*s + (idx - 160);
        else if (idx < 170) node = 85 + 2*s + (idx - 168);
        else if (idx == 170) node = (s < 64) ? (21 + s) : 0;
        else                node = (s == 0) ? (idx - 171) : 0;
        slab[idx] = tn[node * 7];
    }
    // ---- reset flags ----
    if (tid == 0) {
        g_f1[s] = 0u;
        if (s < 64) g_f4[s] = 0u;
        if (s == 0) { g_c2 = 0u; g_f3 = 0u; }
        if (s == 1) g_cfin = 0u;
    }

    // ================= phase 0a: softmax prep =================
    if (s < 16) {
        if (tid < 256) {
            int w = tid >> 5, ln = tid & 31;
            const float* bp = b + (s*8 + w) * 256;
            float mx = -1e30f;
            for (int m = ln; m < 256; m += 32) mx = fmaxf(mx, bp[m]);
            #pragma unroll
            for (int o = 16; o; o >>= 1) mx = fmaxf(mx, __shfl_xor_sync(0xffffffffu, mx, o));
            float ssum = 0.f;
            for (int m = ln; m < 256; m += 32) ssum += expf(bp[m] - mx);
            #pragma unroll
            for (int o = 16; o; o >>= 1) ssum += __shfl_xor_sync(0xffffffffu, ssum, o);
            float inv = 1.f / ssum, ls = logf(ssum);
            for (int m = ln; m < 256; m += 32) {
                float e = bp[m] - mx;
                g_bt [s*2048 + m*8 + w] = expf(e) * inv;
                g_lbt[s*2048 + m*8 + w] = e - ls;
            }
        }
    } else if (s == 16) {
        float* s_sp = sm + OFF_RED;
        if (tid < 16) {
            float v[4]; float mx = -1e30f;
            #pragma unroll
            for (int l = 0; l < 4; l++) { v[l] = sp[tid*4 + l]; mx = fmaxf(mx, v[l]); }
            float su = 0.f;
            #pragma unroll
            for (int l = 0; l < 4; l++) { v[l] = expf(v[l] - mx); su += v[l]; }
            float inv = 1.f / su;
            #pragma unroll
            for (int l = 0; l < 4; l++) {
                float smv = v[l] * inv;
                s_sp[tid*4 + l]  = smv;
                g_lsp[tid*4 + l] = logf(smv);
            }
        }
        if (tid < 64) {
            int gg = tid >> 2, l = tid & 3;
            float v[8]; float mx = -1e30f;
            #pragma unroll
            for (int c = 0; c < 8; c++) { v[c] = pi[gg*32 + c*4 + l]; mx = fmaxf(mx, v[c]); }
            float su = 0.f;
            #pragma unroll
            for (int c = 0; c < 8; c++) { v[c] = expf(v[c] - mx); su += v[c]; }
            float inv = 1.f / su, ls = logf(su);
            #pragma unroll
            for (int c = 0; c < 8; c++) {
                g_pit [gg*32 + l*8 + c] = v[c] * inv;
                g_lpit[gg*32 + l*8 + c] = logf(v[c]) - ls;
            }
        }
        __syncthreads();
        {   // sm_a: 512 (g,j,l) groups, one per thread
            int gg = tid >> 5, j = (tid >> 2) & 7, l = tid & 3;
            float v[8]; float mx = -1e30f;
            #pragma unroll
            for (int ii = 0; ii < 8; ii++) {
                v[ii] = a[gg*256 + ii*32 + j*4 + l];
                mx = fmaxf(mx, v[ii]);
            }
            float su = 0.f;
            #pragma unroll
            for (int ii = 0; ii < 8; ii++) { v[ii] = expf(v[ii] - mx); su += v[ii]; }
            float inv = 1.f / su, ls = logf(su);
            float spv = s_sp[gg*4 + l];
            #pragma unroll
            for (int ii = 0; ii < 8; ii++) {
                int idx = ((gg*8 + ii)*4 + l)*8 + j;
                g_asp [idx] = v[ii] * inv * spv;
                g_loga[idx] = logf(v[ii]) - ls;
            }
        }
    } else if (s == 17) {
        if (tid < 16) g_accum[tid] = 0.f;
    }
    gbar();

    // constant tables in registers
    float as[4][8], la[4][8];
    load_tab(g_asp, wt, as);
    load_tab(g_loga, wt, la);
    #pragma unroll
    for (int l = 0; l < 4; l++)
        #pragma unroll
        for (int j = 0; j < 8; j++) la[l][j] *= as[l][j];
    float lsp[4];
    #pragma unroll
    for (int l = 0; l < 4; l++) lsp[l] = g_lsp[g*4 + l];

    // ================= phase 0b: leaf tables =================
    #pragma unroll
    for (int r = 0; r < 2; r++) {
        int t = (s*4 + q) + 512*r;
        int l = t >> 8, lab = t & 255;
        float lb = g_pit[g*32 + l*8 + i] * g_bt[g*2048 + lab*8 + i];
        lb /= sum8(lb);
        float ce = 0.f, ca = 0.f;
        #pragma unroll
        for (int j = 0; j < 8; j++) {
            float v = __shfl_sync(0xffffffffu, lb, j, 8);
            ce += as[l][j]*v; ca += la[l][j]*v;
        }
        float w = lsp[l] + g_lpit[g*32 + l*8 + i] + g_lbt[g*2048 + lab*8 + i];
        g_uptab[t*128 + wt] = ce;
        g_dntab[t*128 + wt] = ca + w*ce;
    }
    gbar();

    // ================= phase 1: pair-of-subtrees up =================
    // lvl6 (32 nodes/block)
    #pragma unroll 4
    for (int rr = 0; rr < 8; rr++) {
        int k = rr*4 + q;
        int lab0 = slab[4*k], lab1 = slab[4*k+1], lab2 = slab[4*k+2], lab3 = slab[4*k+3];
        int labu = slab[128 + k];
        float sb = g_uptab[(0*256 + lab0)*128 + wt]
                 + g_uptab[(1*256 + lab1)*128 + wt]
                 + g_uptab[(2*256 + lab2)*128 + wt]
                 + g_uptab[(3*256 + lab3)*128 + wt];
        float tmp = g_bt[g*2048 + labu*8 + i] * sb;
        float ts = sum8(tmp);
        sm[OFF_B6 + k*128 + wt] = tmp / ts;
        sm[OFF_S6 + k*128 + wt] = sb;
    }
    __syncthreads();
    // lvl5 (8)
    #pragma unroll 2
    for (int rr = 0; rr < 2; rr++) {
        int k = rr*4 + q;
        float sb = dot_up(sm + OFF_B6 + 4*k*128, as, g);
        int labu = slab[160 + k];
        float tmp = g_bt[g*2048 + labu*8 + i] * sb;
        float ts = sum8(tmp);
        sm[OFF_B5 + k*128 + wt] = tmp / ts;
        sm[OFF_S5 + k*128 + wt] = sb;
    }
    __syncthreads();
    // lvl4 (2, q<2) -> global beta4
    if (q < 2) {
        int t4 = 2*s + q;
        float sb = dot_up(sm + OFF_B5 + 4*q*128, as, g);
        int labu = slab[168 + q];
        float tmp = g_bt[g*2048 + labu*8 + i] * sb;
        float ts = sum8(tmp);
        g_beta4[t4*128 + wt] = tmp / ts;
        sm[OFF_S4 + q*128 + wt] = sb;
    }
    __threadfence();
    __syncthreads();
    if (tid == 0) atomicExch(&g_f1[s], 1u);

    // ================= lvl3 up (blocks 0..63) =================
    if (s < 64) {
        if (tid == 0) {
            while (*(volatile unsigned*)&g_f1[2*s]     == 0u) {}
            while (*(volatile unsigned*)&g_f1[2*s + 1] == 0u) {}
            __threadfence();
        }
        __syncthreads();
        if (q == 0) {
            float sb = 0.f;
            #pragma unroll
            for (int l = 0; l < 4; l++) {
                const float* bv = &g_beta4[(4*s + l)*128 + g*8];
                #pragma unroll
                for (int j = 0; j < 8; j++) sb += as[l][j] * bv[j];
            }
            int labu = slab[170];
            float tmp = g_bt[g*2048 + labu*8 + i] * sb;
            float ts = sum8(tmp);
            g_beta3 [s*128 + wt] = tmp / ts;
            g_sbeta3[s*128 + wt] = sb;
            __threadfence();
        }
        __syncthreads();
        if (tid == 0) atomicAdd(&g_c2, 1u);
    }

    // ================= phase 2: lvl2/1/0 up+down (block 0) =================
    float acc = 0.f;
    if (s == 0) {
        if (tid == 0) {
            while (*(volatile unsigned*)&g_c2 != 64u) {}
            __threadfence();
        }
        __syncthreads();
        for (int idx = tid; idx < 64*128; idx += 512)
            sm[OFF_TOP + idx] = g_beta3[idx];
        __syncthreads();
        // up lvl2 (16)
        #pragma unroll 1
        for (int rr = 0; rr < 4; rr++) {
            int k = rr*4 + q;
            float sb = dot_up(sm + OFF_TOP + 4*k*128, as, g);
            int labu = slab[171 + 5 + k];
            float tmp = g_bt[g*2048 + labu*8 + i] * sb;
            float ts = sum8(tmp);
            sm[OFF_TOPB  + k*128 + wt] = tmp / ts;
            sm[OFF_TOPSB + k*128 + wt] = sb;
        }
        __syncthreads();
        // up lvl1 (4)
        {
            float sb = dot_up(sm + OFF_TOPB + 4*q*128, as, g);
            int labu = slab[171 + 1 + q];
            float tmp = g_bt[g*2048 + labu*8 + i] * sb;
            float ts = sum8(tmp);
            sm[OFF_TOPB  + (16 + q)*128 + wt] = tmp / ts;
            sm[OFF_TOPSB + (16 + q)*128 + wt] = sb;
        }
        __syncthreads();
        // lvl0 up+down fused (group 0)
        if (q == 0) {
            float sb = dot_up(sm + OFF_TOPB + 16*128, as, g);
            int lab0 = slab[171];
            float tmp = g_bt[g*2048 + lab0*8 + i] * sb;
            float ts = sum8(tmp);
            float betar = tmp / ts;
            float pe = betar / sb;
            acc += betar * g_lbt[g*2048 + lab0*8 + i];
            #pragma unroll
            for (int l = 0; l < 4; l++) {
                const float* bv = sm + OFF_TOPB + (16 + l)*128 + g*8;
                float ce = 0.f, ca = 0.f;
                #pragma unroll
                for (int j = 0; j < 8; j++) { ce += as[l][j]*bv[j]; ca += la[l][j]*bv[j]; }
                ce *= pe;
                sm[OFF_EPS1 + l*128 + wt] = ce;
                acc += pe*ca + lsp[l]*ce;
            }
        }
        __syncthreads();
        // down lvl1 (4)
        {
            float epsv = sm[OFF_EPS1 + q*128 + wt];
            float pe = epsv / sm[OFF_TOPSB + (16 + q)*128 + wt];
            int labu = slab[171 + 1 + q];
            acc += epsv * g_lbt[g*2048 + labu*8 + i];
            #pragma unroll
            for (int l = 0; l < 4; l++) {
                const float* bv = sm + OFF_TOPB + (4*q + l)*128 + g*8;
                float ce = 0.f, ca = 0.f;
                #pragma unroll
                for (int j = 0; j < 8; j++) { ce += as[l][j]*bv[j]; ca += la[l][j]*bv[j]; }
                ce *= pe;
                sm[OFF_EPS2 + (4*q + l)*128 + wt] = ce;
                acc += pe*ca + lsp[l]*ce;
            }
        }
        __syncthreads();
        // down lvl2 (16) -> eps of lvl3 nodes
        #pragma unroll 1
        for (int rr = 0; rr < 4; rr++) {
            int k = rr*4 + q;
            float epsv = sm[OFF_EPS2 + k*128 + wt];
            float pe = epsv / sm[OFF_TOPSB + k*128 + wt];
            int labu = slab[171 + 5 + k];
            acc += epsv * g_lbt[g*2048 + labu*8 + i];
            #pragma unroll
            for (int l = 0; l < 4; l++) {
                const float* bv = sm + OFF_TOP + (4*k + l)*128 + g*8;
                float ce = 0.f, ca = 0.f;
                #pragma unroll
                for (int j = 0; j < 8; j++) { ce += as[l][j]*bv[j]; ca += la[l][j]*bv[j]; }
                ce *= pe;
                g_eps3[(4*k + l)*128 + wt] = ce;
                acc += pe*ca + lsp[l]*ce;
            }
        }
        __threadfence();
        __syncthreads();
        if (tid == 0) atomicExch(&g_f3, 1u);
    }

    // ================= lvl3 down (blocks 0..63) =================
    if (s < 64) {
        if (tid == 0) {
            while (*(volatile unsigned*)&g_f3 == 0u) {}
            __threadfence();
        }
        __syncthreads();
        if (q == 0) {
            float eps3 = g_eps3[s*128 + wt];
            float pe = eps3 / g_sbeta3[s*128 + wt];
            int lab3 = slab[170];
            acc += eps3 * g_lbt[g*2048 + lab3*8 + i];
            #pragma unroll
            for (int l = 0; l < 4; l++) {
                const float* bv = &g_beta4[(4*s + l)*128 + g*8];
                float ce = 0.f, ca = 0.f;
                #pragma unroll
                for (int j = 0; j < 8; j++) { ce += as[l][j]*bv[j]; ca += la[l][j]*bv[j]; }
                ce *= pe;
                g_eps4[(4*s + l)*128 + wt] = ce;
                acc += pe*ca + lsp[l]*ce;
            }
            __threadfence();
        }
        __syncthreads();
        if (tid == 0) atomicExch(&g_f4[s], 1u);
    }

    // ================= phase 3: pair-of-subtrees down =================
    if (tid == 0) {
        while (*(volatile unsigned*)&g_f4[s >> 1] == 0u) {}
        __threadfence();
    }
    __syncthreads();
    // lvl4 down (2, q<2)
    if (q < 2) {
        int t4 = 2*s + q;
        float epsv = g_eps4[t4*128 + wt];
        float pe = epsv / sm[OFF_S4 + q*128 + wt];
        int labu = slab[168 + q];
        acc += epsv * g_lbt[g*2048 + labu*8 + i];
        #pragma unroll
        for (int l = 0; l < 4; l++) {
            const float* bv = sm + OFF_B5 + (4*q + l)*128 + g*8;
            float ce = 0.f, ca = 0.f;
            #pragma unroll
            for (int j = 0; j < 8; j++) { ce += as[l][j]*bv[j]; ca += la[l][j]*bv[j]; }
            ce *= pe;
            sm[OFF_E5 + (4*q + l)*128 + wt] = ce;
            acc += pe*ca + lsp[l]*ce;
        }
    }
    __syncthreads();
    // lvl5 down (8)
    #pragma unroll 2
    for (int rr = 0; rr < 2; rr++) {
        int k = rr*4 + q;
        float epsv = sm[OFF_E5 + k*128 + wt];
        float pe = epsv / sm[OFF_S5 + k*128 + wt];
        int labu = slab[160 + k];
        acc += epsv * g_lbt[g*2048 + labu*8 + i];
        #pragma unroll
        for (int l = 0; l < 4; l++) {
            const float* bv = sm + OFF_B6 + (4*k + l)*128 + g*8;
            float ce = 0.f, ca = 0.f;
            #pragma unroll
            for (int j = 0; j < 8; j++) { ce += as[l][j]*bv[j]; ca += la[l][j]*bv[j]; }
            ce *= pe;
            sm[OFF_E6 + (4*k + l)*128 + wt] = ce;
            acc += pe*ca + lsp[l]*ce;
        }
    }
    __syncthreads();
    // lvl6 down (32): leaf children via dn_tab
    #pragma unroll 4
    for (int rr = 0; rr < 8; rr++) {
        int k = rr*4 + q;
        int lab0 = slab[4*k], lab1 = slab[4*k+1], lab2 = slab[4*k+2], lab3 = slab[4*k+3];
        int labu = slab[128 + k];
        float epsv = sm[OFF_E6 + k*128 + wt];
        float pe = epsv / sm[OFF_S6 + k*128 + wt];
        acc += epsv * g_lbt[g*2048 + labu*8 + i];
        float d = g_dntab[(0*256 + lab0)*128 + wt]
                + g_dntab[(1*256 + lab1)*128 + wt]
                + g_dntab[(2*256 + lab2)*128 + wt]
                + g_dntab[(3*256 + lab3)*128 + wt];
        acc += pe * d;
    }

    // ================= reduce + finish ticket =================
    acc = sum8(acc);
    if (i == 0) sm[OFF_RED + q*16 + g] = acc;
    __syncthreads();
    if (tid < 16) {
        float p = sm[OFF_RED + tid] + sm[OFF_RED + 16 + tid]
                + sm[OFF_RED + 32 + tid] + sm[OFF_RED + 48 + tid];
        atomicAdd(&g_accum[tid], p);
        __threadfence();
    }
    __syncthreads();
    unsigned* plast = (unsigned*)(sm + OFF_LAST);
    if (tid == 0) {
        unsigned old = atomicAdd(&g_cfin, 1u);
        *plast = (old == NBLK - 1u) ? 1u : 0u;
        if (old == NBLK - 1u) __threadfence();
    }
    __syncthreads();
    if (*plast && tid < 16)
        out[tid] = *(volatile float*)&g_accum[tid];
}

// ---------------------------------------------------------------------------
extern "C" void kernel_launch(void* const* d_in, const int* in_sizes, int n_in,
                              void* d_out, int out_size)
{
    const int*   tn = (const int*)  d_in[0];
    const float* a  = (const float*)d_in[2];
    const float* b  = (const float*)d_in[3];
    const float* pi = (const float*)d_in[4];
    const float* sp = (const float*)d_in[5];
    float* out = (float*)d_out;

    cudaFuncSetAttribute(main_kernel,
                         cudaFuncAttributeMaxDynamicSharedMemorySize,
                         SMEM_FLOATS * 4);
    main_kernel<<<NBLK, 512, SMEM_FLOATS * 4>>>(tn, a, b, pi, sp, out);
}

// round 8
// speedup vs baseline: 2.9686x; 1.1321x over previous
#include <cuda_runtime.h>

// ---------------------------------------------------------------------------
// BottomUpHTMM — complete 4-ary tree depth 7, single persistent kernel.
// 128 blocks x 512 threads; each block owns two level-4 subtrees.
// Top of the tree (levels 2/1/0) computed REDUNDANTLY by every block after a
// single counter wait -> only 4 global sync events total (2 gbars, f1, c2).
// acquire/release PTX sync (no threadfence). Leaf children folded into
// precomputed up/dn tables.
// ---------------------------------------------------------------------------

#define GC    128
#define NBLK  128

// tables
__device__ float g_asp [4096];      // a_sp[g][i][l][j]   (wt=g*8+i -> wt*32+l*8+j)
__device__ float g_loga[4096];      // log sm_a
__device__ float g_bt  [16*256*8];  // sm_b[g][m][c]
__device__ float g_lbt [16*256*8];
__device__ float g_pit [512];       // sm_pi[g][pos][c]
__device__ float g_lpit[512];
__device__ float g_lsp [64];        // log sm_sp[g][l]

// leaf contribution tables: index (l*256+lab)*128 + wt
__device__ float g_uptab[1024 * GC];
__device__ float g_dntab[1024 * GC];

// cross-block state
__device__ float g_beta4 [256 * GC];
__device__ float g_beta3 [64 * GC];
__device__ float g_sbeta3[64 * GC];
__device__ float g_accum [16];

// sync state
__device__ unsigned g_cnt = 0;
__device__ unsigned g_gen = 0;
__device__ unsigned g_f1[NBLK];     // beta4 pair of block s ready
__device__ unsigned g_c2;           // # lvl3 nodes done
__device__ unsigned g_cfin;         // finish ticket

// shared-memory layout (floats; rows of 128)
#define OFF_B6    0        // 32 rows lvl6 beta
#define OFF_S6    4096     // 32 rows lvl6 sbeta
#define OFF_B5    8192     // 8 rows lvl5 beta
#define OFF_S5    9216     // 8 rows lvl5 sbeta
#define OFF_S4    10240    // 2 rows lvl4 sbeta
#define OFF_E5    10496    // 8 rows lvl5 eps
#define OFF_E6    11520    // 32 rows lvl6 eps
#define OFF_TOP   15616    // 64 rows beta3 copy
#define OFF_B2    23808    // 16 rows lvl2 beta
#define OFF_S2    25856    // 16 rows lvl2 sbeta
#define OFF_B1    27904    // 4 rows lvl1 beta
#define OFF_S1    28416    // 4 rows lvl1 sbeta
#define OFF_E1    28928    // 4 rows lvl1 eps
#define OFF_E2    29440    // 16 rows lvl2 eps
#define OFF_E3    31488    // 1 row  own lvl3 eps
#define OFF_E4    31616    // 2 rows own lvl4 eps
#define OFF_RED   31872    // 64
#define OFF_LAB   31936    // 208 ints
#define OFF_LAST  32144    // 1
#define SMEM_FLOATS 32148  // ~125.6 KB

__device__ __forceinline__ float sum8(float v) {
    v += __shfl_xor_sync(0xffffffffu, v, 4);
    v += __shfl_xor_sync(0xffffffffu, v, 2);
    v += __shfl_xor_sync(0xffffffffu, v, 1);
    return v;
}

__device__ __forceinline__ void load_tab(const float* __restrict__ base, int wt,
                                         float (&r)[4][8]) {
    const float4* p = (const float4*)(base + wt * 32);
    #pragma unroll
    for (int l = 0; l < 4; l++) {
        float4 a = p[2*l], b = p[2*l + 1];
        r[l][0]=a.x; r[l][1]=a.y; r[l][2]=a.z; r[l][3]=a.w;
        r[l][4]=b.x; r[l][5]=b.y; r[l][6]=b.z; r[l][7]=b.w;
    }
}

// ---- acquire/release helpers ----
__device__ __forceinline__ void st_release(unsigned* p, unsigned v) {
    asm volatile("st.release.gpu.global.u32 [%0], %1;" :: "l"(p), "r"(v) : "memory");
}
__device__ __forceinline__ unsigned ld_acquire(unsigned* p) {
    unsigned v;
    asm volatile("ld.acquire.gpu.global.u32 %0, [%1];" : "=r"(v) : "l"(p) : "memory");
    return v;
}
__device__ __forceinline__ void red_release_add(unsigned* p, unsigned v) {
    asm volatile("red.release.gpu.global.add.u32 [%0], %1;" :: "l"(p), "r"(v) : "memory");
}
__device__ __forceinline__ unsigned atom_acqrel_add(unsigned* p, unsigned v) {
    unsigned old;
    asm volatile("atom.acq_rel.gpu.global.add.u32 %0, [%1], %2;"
                 : "=r"(old) : "l"(p), "r"(v) : "memory");
    return old;
}

// full grid barrier (NBLK blocks co-resident)
__device__ __forceinline__ void gbar() {
    __syncthreads();
    if (threadIdx.x == 0) {
        unsigned gen = ld_acquire(&g_gen);
        unsigned old = atom_acqrel_add(&g_cnt, 1u);
        if (old == NBLK - 1u) {
            asm volatile("st.relaxed.gpu.global.u32 [%0], %1;" :: "l"(&g_cnt), "r"(0u) : "memory");
            st_release(&g_gen, gen + 1u);
        } else {
            while (ld_acquire(&g_gen) == gen) __nanosleep(32);
        }
    }
    __syncthreads();
}

__device__ __forceinline__ float dot_up(const float* __restrict__ cb0,
                                        const float (&as)[4][8], int g) {
    float sb = 0.f;
    #pragma unroll
    for (int l = 0; l < 4; l++) {
        const float* bv = cb0 + l*128 + g*8;
        #pragma unroll
        for (int j = 0; j < 8; j++) sb += as[l][j] * bv[j];
    }
    return sb;
}

__global__ void __launch_bounds__(512, 1)
main_kernel(const int* __restrict__ tn,
            const float* __restrict__ a,
            const float* __restrict__ b,
            const float* __restrict__ pi,
            const float* __restrict__ sp,
            float* __restrict__ out)
{
    extern __shared__ float sm[];
    const int tid = threadIdx.x, s = blockIdx.x;
    const int q = tid >> 7, wt = tid & 127, g = wt >> 3, i = wt & 7;
    int* slab = (int*)(sm + OFF_LAB);

    // ---- stage labels ----
    if (tid < 193) {
        int idx = tid, node;
        if      (idx < 128) node = 5461 + 128*s + idx;
        else if (idx < 160) node = 1365 + 32*s + (idx - 128);
        else if (idx < 168) node = 341 + 8*s + (idx - 160);
        else if (idx < 170) node = 85 + 2*s + (idx - 168);
        else if (idx == 170) node = (s < 64) ? (21 + s) : 21;
        else if (idx < 192) node = idx - 171;          // top nodes 0..20
        else                node = 21 + (s >> 1);      // own lvl3 ancestor
        slab[idx] = tn[node * 7];
    }
    // ---- reset flags (pre-gbar, ordered by gbar) ----
    if (tid == 0) {
        g_f1[s] = 0u;
        if (s == 0) g_c2 = 0u;
        if (s == 1) g_cfin = 0u;
    }

    // ================= phase 0a: softmax prep =================
    if (s < 16) {
        if (tid < 256) {
            int w = tid >> 5, ln = tid & 31;
            const float* bp = b + (s*8 + w) * 256;
            float mx = -1e30f;
            for (int m = ln; m < 256; m += 32) mx = fmaxf(mx, bp[m]);
            #pragma unroll
            for (int o = 16; o; o >>= 1) mx = fmaxf(mx, __shfl_xor_sync(0xffffffffu, mx, o));
            float ssum = 0.f;
            for (int m = ln; m < 256; m += 32) ssum += expf(bp[m] - mx);
            #pragma unroll
            for (int o = 16; o; o >>= 1) ssum += __shfl_xor_sync(0xffffffffu, ssum, o);
            float inv = 1.f / ssum, ls = logf(ssum);
            for (int m = ln; m < 256; m += 32) {
                float e = bp[m] - mx;
                g_bt [s*2048 + m*8 + w] = expf(e) * inv;
                g_lbt[s*2048 + m*8 + w] = e - ls;
            }
        }
    } else if (s == 16) {
        float* s_sp = sm + OFF_RED;
        if (tid < 16) {
            float v[4]; float mx = -1e30f;
            #pragma unroll
            for (int l = 0; l < 4; l++) { v[l] = sp[tid*4 + l]; mx = fmaxf(mx, v[l]); }
            float su = 0.f;
            #pragma unroll
            for (int l = 0; l < 4; l++) { v[l] = expf(v[l] - mx); su += v[l]; }
            float inv = 1.f / su;
            #pragma unroll
            for (int l = 0; l < 4; l++) {
                float smv = v[l] * inv;
                s_sp[tid*4 + l]  = smv;
                g_lsp[tid*4 + l] = logf(smv);
            }
        }
        if (tid < 64) {
            int gg = tid >> 2, l = tid & 3;
            float v[8]; float mx = -1e30f;
            #pragma unroll
            for (int c = 0; c < 8; c++) { v[c] = pi[gg*32 + c*4 + l]; mx = fmaxf(mx, v[c]); }
            float su = 0.f;
            #pragma unroll
            for (int c = 0; c < 8; c++) { v[c] = expf(v[c] - mx); su += v[c]; }
            float inv = 1.f / su, ls = logf(su);
            #pragma unroll
            for (int c = 0; c < 8; c++) {
                g_pit [gg*32 + l*8 + c] = v[c] * inv;
                g_lpit[gg*32 + l*8 + c] = logf(v[c]) - ls;
            }
        }
        __syncthreads();
        {   // sm_a: 512 (g,j,l) groups, one per thread
            int gg = tid >> 5, j = (tid >> 2) & 7, l = tid & 3;
            float v[8]; float mx = -1e30f;
            #pragma unroll
            for (int ii = 0; ii < 8; ii++) {
                v[ii] = a[gg*256 + ii*32 + j*4 + l];
                mx = fmaxf(mx, v[ii]);
            }
            float su = 0.f;
            #pragma unroll
            for (int ii = 0; ii < 8; ii++) { v[ii] = expf(v[ii] - mx); su += v[ii]; }
            float inv = 1.f / su, ls = logf(su);
            float spv = s_sp[gg*4 + l];
            #pragma unroll
            for (int ii = 0; ii < 8; ii++) {
                int idx = ((gg*8 + ii)*4 + l)*8 + j;
                g_asp [idx] = v[ii] * inv * spv;
                g_loga[idx] = logf(v[ii]) - ls;
            }
        }
    } else if (s == 17) {
        if (tid < 16) g_accum[tid] = 0.f;
    }
    gbar();

    // as + lsp in registers (la deferred until after c2 wait)
    float as[4][8];
    load_tab(g_asp, wt, as);
    float lsp[4];
    #pragma unroll
    for (int l = 0; l < 4; l++) lsp[l] = g_lsp[g*4 + l];

    // ================= phase 0b: leaf tables (ephemeral loga) =================
    #pragma unroll
    for (int r = 0; r < 2; r++) {
        int t = (s*4 + q) + 512*r;
        int l = t >> 8, lab = t & 255;
        const float4* lp = (const float4*)(g_loga + wt*32 + l*8);
        float4 y0 = lp[0], y1 = lp[1];
        float lav[8] = {y0.x, y0.y, y0.z, y0.w, y1.x, y1.y, y1.z, y1.w};
        float lb = g_pit[g*32 + l*8 + i] * g_bt[g*2048 + lab*8 + i];
        lb = __fdividef(lb, sum8(lb));
        float ce = 0.f, ca = 0.f;
        #pragma unroll
        for (int j = 0; j < 8; j++) {
            float v = __shfl_sync(0xffffffffu, lb, j, 8);
            ce += as[l][j]*v; ca += as[l][j]*lav[j]*v;
        }
        float w = lsp[l] + g_lpit[g*32 + l*8 + i] + g_lbt[g*2048 + lab*8 + i];
        g_uptab[t*128 + wt] = ce;
        g_dntab[t*128 + wt] = ca + w*ce;
    }
    gbar();

    // ================= phase 1: pair-of-subtrees up =================
    float emis6[8];
    #pragma unroll
    for (int rr = 0; rr < 8; rr++)
        emis6[rr] = g_bt[g*2048 + slab[128 + rr*4 + q]*8 + i];
    #pragma unroll 4
    for (int rr = 0; rr < 8; rr++) {
        int k = rr*4 + q;
        int lab0 = slab[4*k], lab1 = slab[4*k+1], lab2 = slab[4*k+2], lab3 = slab[4*k+3];
        float sb = g_uptab[(0*256 + lab0)*128 + wt]
                 + g_uptab[(1*256 + lab1)*128 + wt]
                 + g_uptab[(2*256 + lab2)*128 + wt]
                 + g_uptab[(3*256 + lab3)*128 + wt];
        float tmp = emis6[rr] * sb;
        float ts = sum8(tmp);
        sm[OFF_B6 + k*128 + wt] = __fdividef(tmp, ts);
        sm[OFF_S6 + k*128 + wt] = sb;
    }
    __syncthreads();
    // lvl5 (8)
    #pragma unroll 2
    for (int rr = 0; rr < 2; rr++) {
        int k = rr*4 + q;
        float sb = dot_up(sm + OFF_B6 + 4*k*128, as, g);
        float tmp = g_bt[g*2048 + slab[160 + k]*8 + i] * sb;
        float ts = sum8(tmp);
        sm[OFF_B5 + k*128 + wt] = __fdividef(tmp, ts);
        sm[OFF_S5 + k*128 + wt] = sb;
    }
    __syncthreads();
    // lvl4 (2, q<2) -> global beta4
    if (q < 2) {
        int t4 = 2*s + q;
        float sb = dot_up(sm + OFF_B5 + 4*q*128, as, g);
        float tmp = g_bt[g*2048 + slab[168 + q]*8 + i] * sb;
        float ts = sum8(tmp);
        g_beta4[t4*128 + wt] = __fdividef(tmp, ts);
        sm[OFF_S4 + q*128 + wt] = sb;
    }
    __syncthreads();
    if (tid == 0) st_release(&g_f1[s], 1u);

    // ================= lvl3 up (blocks 0..63) =================
    if (s < 64) {
        if (tid == 0) {
            while (ld_acquire(&g_f1[2*s])     == 0u) {}
            while (ld_acquire(&g_f1[2*s + 1]) == 0u) {}
        }
        __syncthreads();
        if (q == 0) {
            float sb = 0.f;
            #pragma unroll
            for (int l = 0; l < 4; l++) {
                const float* bv = &g_beta4[(4*s + l)*128 + g*8];
                #pragma unroll
                for (int j = 0; j < 8; j++) sb += as[l][j] * bv[j];
            }
            float tmp = g_bt[g*2048 + slab[170]*8 + i] * sb;
            float ts = sum8(tmp);
            g_beta3 [s*128 + wt] = __fdividef(tmp, ts);
            g_sbeta3[s*128 + wt] = sb;
        }
        __syncthreads();
        if (tid == 0) red_release_add(&g_c2, 1u);
    }

    // ================= wait all lvl3 ready =================
    if (tid == 0) {
        while (ld_acquire(&g_c2) != 64u) __nanosleep(64);
    }
    __syncthreads();

    // la table now (needed for all down passes)
    float la[4][8];
    load_tab(g_loga, wt, la);
    #pragma unroll
    for (int l = 0; l < 4; l++)
        #pragma unroll
        for (int j = 0; j < 8; j++) la[l][j] *= as[l][j];

    // copy all 64 beta3 rows to smem
    {
        float4* dst = (float4*)(sm + OFF_TOP);
        const float4* src = (const float4*)g_beta3;
        #pragma unroll
        for (int r = 0; r < 4; r++) dst[tid + r*512] = src[tid + r*512];
    }
    __syncthreads();

    // ================= redundant top: up lvl2/lvl1/root =================
    float acc = 0.f;
    #pragma unroll 1
    for (int rr = 0; rr < 4; rr++) {
        int k = rr*4 + q;
        float sb = dot_up(sm + OFF_TOP + 4*k*128, as, g);
        float tmp = g_bt[g*2048 + slab[176 + k]*8 + i] * sb;
        float ts = sum8(tmp);
        sm[OFF_B2 + k*128 + wt] = __fdividef(tmp, ts);
        sm[OFF_S2 + k*128 + wt] = sb;
    }
    __syncthreads();
    {
        float sb = dot_up(sm + OFF_B2 + 4*q*128, as, g);
        float tmp = g_bt[g*2048 + slab[172 + q]*8 + i] * sb;
        float ts = sum8(tmp);
        sm[OFF_B1 + q*128 + wt] = __fdividef(tmp, ts);
        sm[OFF_S1 + q*128 + wt] = sb;
    }
    __syncthreads();
    // root up+down (group 0)
    if (q == 0) {
        float sb = dot_up(sm + OFF_B1, as, g);
        int lab0 = slab[171];
        float tmp = g_bt[g*2048 + lab0*8 + i] * sb;
        float ts = sum8(tmp);
        float betar = __fdividef(tmp, ts);
        float pe = __fdividef(betar, sb);
        if (s == 0) acc += betar * g_lbt[g*2048 + lab0*8 + i];
        #pragma unroll
        for (int l = 0; l < 4; l++) {
            const float* bv = sm + OFF_B1 + l*128 + g*8;
            float ce = 0.f, ca = 0.f;
            #pragma unroll
            for (int j = 0; j < 8; j++) { ce += as[l][j]*bv[j]; ca += la[l][j]*bv[j]; }
            ce *= pe;
            sm[OFF_E1 + l*128 + wt] = ce;
            if (s == 0) acc += pe*ca + lsp[l]*ce;
        }
    }
    __syncthreads();
    // down lvl1 (group q = node q)
    {
        float epsv = sm[OFF_E1 + q*128 + wt];
        float pe = __fdividef(epsv, sm[OFF_S1 + q*128 + wt]);
        if (s == 0) acc += epsv * g_lbt[g*2048 + slab[172 + q]*8 + i];
        #pragma unroll
        for (int l = 0; l < 4; l++) {
            const float* bv = sm + OFF_B2 + (4*q + l)*128 + g*8;
            float ce = 0.f, ca = 0.f;
            #pragma unroll
            for (int j = 0; j < 8; j++) { ce += as[l][j]*bv[j]; ca += la[l][j]*bv[j]; }
            ce *= pe;
            sm[OFF_E2 + (4*q + l)*128 + wt] = ce;
            if (s == 0) acc += pe*ca + lsp[l]*ce;
        }
    }
    __syncthreads();
    // down lvl2: block0 full (acc); others own node only
    if (s == 0) {
        #pragma unroll 1
        for (int rr = 0; rr < 4; rr++) {
            int k = rr*4 + q;
            float epsv = sm[OFF_E2 + k*128 + wt];
            float pe = __fdividef(epsv, sm[OFF_S2 + k*128 + wt]);
            acc += epsv * g_lbt[g*2048 + slab[176 + k]*8 + i];
            #pragma unroll
            for (int l = 0; l < 4; l++) {
                const float* bv = sm + OFF_TOP + (4*k + l)*128 + g*8;
                float ce = 0.f, ca = 0.f;
                #pragma unroll
                for (int j = 0; j < 8; j++) { ce += as[l][j]*bv[j]; ca += la[l][j]*bv[j]; }
                ce *= pe;
                acc += pe*ca + lsp[l]*ce;
                if (4*k + l == 0) sm[OFF_E3 + wt] = ce;
            }
        }
    } else if (q == 0) {
        int t = s >> 1, p2 = t >> 2, lc = t & 3;
        float epsv = sm[OFF_E2 + p2*128 + wt];
        float pe = __fdividef(epsv, sm[OFF_S2 + p2*128 + wt]);
        const float* bv = sm + OFF_TOP + (4*p2 + lc)*128 + g*8;
        float ce = 0.f;
        #pragma unroll
        for (int j = 0; j < 8; j++) ce += as[lc][j]*bv[j];
        sm[OFF_E3 + wt] = ce * pe;
    }
    // lvl3 down (group 0; E3 produced/consumed by same threads)
    if (q == 0) {
        int t = s >> 1;
        int half = s & 1;
        float eps3 = sm[OFF_E3 + wt];
        float pe3 = __fdividef(eps3, g_sbeta3[t*128 + wt]);
        if (half == 0) acc += eps3 * g_lbt[g*2048 + slab[192]*8 + i];
        #pragma unroll
        for (int l = 0; l < 4; l++) {
            const float* bv = &g_beta4[(4*t + l)*128 + g*8];
            float ce = 0.f, ca = 0.f;
            #pragma unroll
            for (int j = 0; j < 8; j++) { ce += as[l][j]*bv[j]; ca += la[l][j]*bv[j]; }
            ce *= pe3;
            int lown = l - 2*half;
            if (lown == 0 || lown == 1) {
                acc += pe3*ca + lsp[l]*ce;
                sm[OFF_E4 + lown*128 + wt] = ce;
            }
        }
    }
    __syncthreads();

    // ================= phase 3: pair-of-subtrees down =================
    if (q < 2) {
        float epsv = sm[OFF_E4 + q*128 + wt];
        float pe = __fdividef(epsv, sm[OFF_S4 + q*128 + wt]);
        acc += epsv * g_lbt[g*2048 + slab[168 + q]*8 + i];
        #pragma unroll
        for (int l = 0; l < 4; l++) {
            const float* bv = sm + OFF_B5 + (4*q + l)*128 + g*8;
            float ce = 0.f, ca = 0.f;
            #pragma unroll
            for (int j = 0; j < 8; j++) { ce += as[l][j]*bv[j]; ca += la[l][j]*bv[j]; }
            ce *= pe;
            sm[OFF_E5 + (4*q + l)*128 + wt] = ce;
            acc += pe*ca + lsp[l]*ce;
        }
    }
    __syncthreads();
    // lvl5 down (8)
    #pragma unroll 2
    for (int rr = 0; rr < 2; rr++) {
        int k = rr*4 + q;
        float epsv = sm[OFF_E5 + k*128 + wt];
        float pe = __fdividef(epsv, sm[OFF_S5 + k*128 + wt]);
        acc += epsv * g_lbt[g*2048 + slab[160 + k]*8 + i];
        #pragma unroll
        for (int l = 0; l < 4; l++) {
            const float* bv = sm + OFF_B6 + (4*k + l)*128 + g*8;
            float ce = 0.f, ca = 0.f;
            #pragma unroll
            for (int j = 0; j < 8; j++) { ce += as[l][j]*bv[j]; ca += la[l][j]*bv[j]; }
            ce *= pe;
            sm[OFF_E6 + (4*k + l)*128 + wt] = ce;
            acc += pe*ca + lsp[l]*ce;
        }
    }
    __syncthreads();
    // lvl6 down (32): leaf children via dn_tab, emission prefetch
    float lemis6[8];
    #pragma unroll
    for (int rr = 0; rr < 8; rr++)
        lemis6[rr] = g_lbt[g*2048 + slab[128 + rr*4 + q]*8 + i];
    #pragma unroll 4
    for (int rr = 0; rr < 8; rr++) {
        int k = rr*4 + q;
        int lab0 = slab[4*k], lab1 = slab[4*k+1], lab2 = slab[4*k+2], lab3 = slab[4*k+3];
        float epsv = sm[OFF_E6 + k*128 + wt];
        float pe = __fdividef(epsv, sm[OFF_S6 + k*128 + wt]);
        acc += epsv * lemis6[rr];
        float d = g_dntab[(0*256 + lab0)*128 + wt]
                + g_dntab[(1*256 + lab1)*128 + wt]
                + g_dntab[(2*256 + lab2)*128 + wt]
                + g_dntab[(3*256 + lab3)*128 + wt];
        acc += pe * d;
    }

    // ================= reduce + finish ticket =================
    acc = sum8(acc);
    if (i == 0) sm[OFF_RED + q*16 + g] = acc;
    __syncthreads();
    if (tid < 16) {
        float p = sm[OFF_RED + tid] + sm[OFF_RED + 16 + tid]
                + sm[OFF_RED + 32 + tid] + sm[OFF_RED + 48 + tid];
        atomicAdd(&g_accum[tid], p);
    }
    __syncthreads();
    unsigned* plast = (unsigned*)(sm + OFF_LAST);
    if (tid == 0) {
        unsigned old = atom_acqrel_add(&g_cfin, 1u);
        *plast = (old == NBLK - 1u) ? 1u : 0u;
    }
    __syncthreads();
    if (*plast && tid < 16)
        out[tid] = *(volatile float*)&g_accum[tid];
}

// ---------------------------------------------------------------------------
extern "C" void kernel_launch(void* const* d_in, const int* in_sizes, int n_in,
                              void* d_out, int out_size)
{
    const int*   tn = (const int*)  d_in[0];
    const float* a  = (const float*)d_in[2];
    const float* b  = (const float*)d_in[3];
    const float* pi = (const float*)d_in[4];
    const float* sp = (const float*)d_in[5];
    float* out = (float*)d_out;

    cudaFuncSetAttribute(main_kernel,
                         cudaFuncAttributeMaxDynamicSharedMemorySize,
                         SMEM_FLOATS * 4);
    main_kernel<<<NBLK, 512, SMEM_FLOATS * 4>>>(tn, a, b, pi, sp, out);
}